// round 7
// baseline (speedup 1.0000x reference)
#include <cuda_runtime.h>
#include <cuda_fp16.h>
#include <math.h>
#include <stdint.h>

// ---------------- problem constants ----------------
#define BATCH 4
#define SEQ   4096
#define HID_  1024
#define LC    1024
#define KSEL  512
#define WIN   256
#define NWIN  16

static const long N_TOK = (long)BATCH * SEQ;

// ---------------- scratch layout (bytes) ----------------
// fp16 split matrices: rows of length 2*K; per 32-orig-col block b,
// cols 64b..64b+31 = hi, 64b+32..64b+63 = lo. B-side GEMM reads use hi only.
constexpr long O_XB    = 0;                         // x split      (16384,2048)h
constexpr long O_QFB   = O_XB    + 67108864L;       // Qf split
constexpr long O_KFB   = O_QFB   + 67108864L;       // Kf split
constexpr long O_VF    = O_KFB   + 67108864L;       // Vf fp32      (16384,1024)f
constexpr long O_TVFB  = O_VF    + 67108864L;       // Vf^T split   4x(1024,8192)h
constexpr long O_COMPB = O_TVFB  + 67108864L;       // comp split   (4096,2048)h
constexpr long O_QCB   = O_COMPB + 16777216L;
constexpr long O_KCB   = O_QCB   + 16777216L;
constexpr long O_VC    = O_KCB   + 16777216L;       // Vc fp32 (4096,1024)f
constexpr long O_TVCB  = O_VC    + 16777216L;       // Vc^T split 4x(1024,2048)h
constexpr long O_SC    = O_TVCB  + 16777216L;       // comp scores fp32
constexpr long O_SCB   = O_SC    + 16777216L;       // comp P split
constexpr long O_CPVB  = O_SCB   + 16777216L;
constexpr long O_SQB   = O_CPVB  + 16777216L;
constexpr long O_SKB   = O_SQB   + 8388608L;
constexpr long O_SV    = O_SKB   + 8388608L;
constexpr long O_TSVB  = O_SV    + 8388608L;
constexpr long O_SS    = O_TSVB  + 8388608L;
constexpr long O_SSB   = O_SS    + 4194304L;
constexpr long O_SPVB  = O_SSB   + 4194304L;
constexpr long O_SW    = O_SPVB  + 8388608L;
constexpr long O_SWB   = O_SW    + 16777216L;
constexpr long O_WPVB  = O_SWB   + 16777216L;
constexpr long O_O     = O_WPVB  + 67108864L;
constexpr long O_TWQ   = O_O     + 67108864L;
constexpr long O_TWK   = O_TWQ   + 4194304L;
constexpr long O_TWV   = O_TWK   + 4194304L;
constexpr long O_TWC   = O_TWV   + 4194304L;
constexpr long O_TWO0  = O_TWC   + 16777216L;
constexpr long O_TWO1  = O_TWO0  + 4194304L;
constexpr long O_TWO2  = O_TWO1  + 4194304L;
constexpr long O_GATES = O_TWO2  + 4194304L;
constexpr long O_SCOR  = O_GATES + 196608L;
constexpr long TOTALB  = O_SCOR  + 65536L;

__device__ __align__(1024) unsigned char g_scratch[TOTALB];
__device__ int g_idx[BATCH * KSEL];

typedef __half h16;

// ================= PTX helpers =================
__device__ __forceinline__ uint32_t smem_u32(const void* p) {
    uint32_t a;
    asm("{ .reg .u64 t; cvta.to.shared.u64 t, %1; cvt.u32.u64 %0, t; }" : "=r"(a) : "l"(p));
    return a;
}
__device__ __forceinline__ void cp16(uint32_t dst, const void* src) {
    asm volatile("cp.async.cg.shared.global [%0], [%1], 16;" :: "r"(dst), "l"(src));
}
#define CP_COMMIT() asm volatile("cp.async.commit_group;" ::: "memory")
#define CP_WAIT2()  asm volatile("cp.async.wait_group 2;" ::: "memory")

__device__ __forceinline__ void ldm4(uint32_t* r, uint32_t addr) {
    asm volatile("ldmatrix.sync.aligned.m8n8.x4.shared.b16 {%0,%1,%2,%3}, [%4];"
        : "=r"(r[0]), "=r"(r[1]), "=r"(r[2]), "=r"(r[3]) : "r"(addr));
}
__device__ __forceinline__ void mma16816(float* d, const uint32_t* a, const uint32_t* b) {
    asm volatile(
        "mma.sync.aligned.m16n8k16.row.col.f32.f16.f16.f32 "
        "{%0,%1,%2,%3}, {%4,%5,%6,%7}, {%8,%9}, {%0,%1,%2,%3};"
        : "+f"(d[0]), "+f"(d[1]), "+f"(d[2]), "+f"(d[3])
        : "r"(a[0]), "r"(a[1]), "r"(a[2]), "r"(a[3]), "r"(b[0]), "r"(b[1]));
}
__device__ __forceinline__ void h_split(float v, h16& h, h16& l) {
    h = __float2half_rn(v);
    l = __float2half_rn(v - __half2float(h));
}

// ================= pipelined HMMA GEMM (fp16 split A x fp16-hi B) =================
// C[M,N] = alpha * A·Bhi^T (+bias)(accum into Cf)(*gate(row))
// A (M,2K) split; B (N,2K) split but only hi halves fetched.
// Tile 128x128, chunk 32 orig-k (=64 split cols), 4-stage cp.async ring (96KB).
struct GP {
    const h16 *A, *B;
    const float *bias, *gate;
    float *Cf; h16 *Cb;
    int K2, lda, ldb, ldcf, ldcb;
    float alpha;
    int accumulate, zdiv, gcomp;
    long aso, asi, bso, bsi, cfso, cfsi, cbso, cbsi, gso, gsi;
};

__device__ __forceinline__ void stage_load(uint32_t smb, int s, const h16* A, const h16* B,
                                           int lda, int ldb, int k2off, int tid) {
    uint32_t sa = smb + s * 24576;
    uint32_t sb2 = sa + 16384;
#pragma unroll
    for (int i = 0; i < 4; i++) {            // A: 128 rows x 8 segs (128B rows)
        int idx = tid + i * 256;
        int row = idx >> 3, seg = idx & 7;
        cp16(sa + row * 128 + ((seg ^ (row & 7)) << 4), A + (long)row * lda + k2off + seg * 8);
    }
#pragma unroll
    for (int i = 0; i < 2; i++) {            // B hi: 128 rows x 4 segs (64B rows)
        int idx = tid + i * 256;
        int row = idx >> 2, seg = idx & 3;
        cp16(sb2 + row * 64 + ((seg ^ ((row >> 1) & 3)) << 4),
             B + (long)row * ldb + k2off + seg * 8);
    }
    CP_COMMIT();
}

__device__ __forceinline__ uint32_t swzA(uint32_t base, int r, int cb) {
    return base + r * 128 + ((((cb >> 4) ^ (r & 7))) << 4) + (cb & 15);
}

__global__ void __launch_bounds__(256, 2) gemm_k(GP p) {
    extern __shared__ __align__(1024) char sm[];
    uint32_t smb = smem_u32(sm);
    const int tid = threadIdx.x, lane = tid & 31, wid = tid >> 5;
    const int wm = wid & 3, wn = wid >> 2;

    const long zo = blockIdx.z / p.zdiv, zi = blockIdx.z - zo * (long)p.zdiv;
    const h16* A = p.A + zo * p.aso + zi * p.asi + (long)blockIdx.y * 128 * p.lda;
    const h16* B = p.B + zo * p.bso + zi * p.bsi + (long)blockIdx.x * 128 * p.ldb;

    float acc[2][8][4];
#pragma unroll
    for (int mt = 0; mt < 2; mt++)
#pragma unroll
        for (int nt = 0; nt < 8; nt++)
#pragma unroll
            for (int r = 0; r < 4; r++) acc[mt][nt][r] = 0.f;

    const int nch = p.K2 >> 6;
    stage_load(smb, 0, A, B, p.lda, p.ldb, 0, tid);
    stage_load(smb, 1, A, B, p.lda, p.ldb, 64, tid);
    stage_load(smb, 2, A, B, p.lda, p.ldb, 128, tid);

    for (int c = 0; c < nch; c++) {
        CP_WAIT2();
        __syncthreads();
        if (c + 3 < nch) stage_load(smb, (c + 3) & 3, A, B, p.lda, p.ldb, (c + 3) * 64, tid);
        else CP_COMMIT();

        uint32_t sa = smb + (c & 3) * 24576, sbB = sa + 16384;
#pragma unroll
        for (int ks = 0; ks < 2; ks++) {
            uint32_t aH[2][4], aL[2][4];
            int ar = wm * 32 + (lane & 15);
            int acb = ks * 32 + ((lane >> 4) << 4);
#pragma unroll
            for (int mt = 0; mt < 2; mt++) {
                ldm4(aH[mt], swzA(sa, ar + mt * 16, acb));
                ldm4(aL[mt], swzA(sa, ar + mt * 16, acb + 64));
            }
            int seg = ks * 2 + ((lane >> 3) & 1);
#pragma unroll
            for (int nb = 0; nb < 4; nb++) {
                int brow = wn * 64 + nb * 16 + (lane & 7) + ((lane >> 4) << 3);
                uint32_t h4[4];
                ldm4(h4, sbB + brow * 64 + ((seg ^ ((brow >> 1) & 3)) << 4));
#pragma unroll
                for (int sub = 0; sub < 2; sub++) {
                    int nt = nb * 2 + sub;
#pragma unroll
                    for (int mt = 0; mt < 2; mt++) {
                        mma16816(acc[mt][nt], aH[mt], h4 + sub * 2);
                        mma16816(acc[mt][nt], aL[mt], h4 + sub * 2);
                    }
                }
            }
        }
    }

    // ---- epilogue ----
    const float* gb = p.gate ? (p.gate + zo * p.gso + zi * p.gsi) : nullptr;
    float* Cf = p.Cf ? (p.Cf + zo * p.cfso + zi * p.cfsi) : nullptr;
    h16* Cb = p.Cb ? (p.Cb + zo * p.cbso + zi * p.cbsi) : nullptr;
    const long rowBase = (long)blockIdx.y * 128 + wm * 32;
    const long colBase = (long)blockIdx.x * 128 + wn * 64;
    const int g = lane >> 2, t = lane & 3;
#pragma unroll
    for (int mt = 0; mt < 2; mt++) {
        long r0 = rowBase + mt * 16 + g, r1 = r0 + 8;
        float gv0 = gb ? gb[r0 * 3 + p.gcomp] : 1.f;
        float gv1 = gb ? gb[r1 * 3 + p.gcomp] : 1.f;
#pragma unroll
        for (int nt = 0; nt < 8; nt++) {
            long c = colBase + nt * 8 + t * 2;
            float b0 = p.bias ? p.bias[c] : 0.f;
            float b1 = p.bias ? p.bias[c + 1] : 0.f;
            float* d = acc[mt][nt];
            float v0 = p.alpha * d[0] + b0, v1 = p.alpha * d[1] + b1;
            float v2 = p.alpha * d[2] + b0, v3 = p.alpha * d[3] + b1;
            if (Cf) {
                long o0 = r0 * (long)p.ldcf + c, o1 = r1 * (long)p.ldcf + c;
                if (p.accumulate) { v0 += Cf[o0]; v1 += Cf[o0 + 1]; v2 += Cf[o1]; v3 += Cf[o1 + 1]; }
                v0 *= gv0; v1 *= gv0; v2 *= gv1; v3 *= gv1;
                *(float2*)(Cf + o0) = make_float2(v0, v1);
                *(float2*)(Cf + o1) = make_float2(v2, v3);
            } else {
                v0 *= gv0; v1 *= gv0; v2 *= gv1; v3 *= gv1;
            }
            if (Cb) {
                int oc = (int)(64 * (c >> 5) + (c & 31));
                h16 h, l;
                __half2 hp, lp;
                h_split(v0, h, l); hp.x = h; lp.x = l;
                h_split(v1, h, l); hp.y = h; lp.y = l;
                *(__half2*)(Cb + r0 * (long)p.ldcb + oc) = hp;
                *(__half2*)(Cb + r0 * (long)p.ldcb + oc + 32) = lp;
                h_split(v2, h, l); hp.x = h; lp.x = l;
                h_split(v3, h, l); hp.y = h; lp.y = l;
                *(__half2*)(Cb + r1 * (long)p.ldcb + oc) = hp;
                *(__half2*)(Cb + r1 * (long)p.ldcb + oc + 32) = lp;
            }
        }
    }
}

static void run_gemm(const h16* A, const h16* B, const float* bias, const float* gate,
                     float* Cf, h16* Cb, int M, int N, int K2,
                     int lda, int ldb, int ldcf, int ldcb, float alpha,
                     int accum, int nz, int zdiv,
                     long aso, long asi, long bso, long bsi,
                     long cfso, long cfsi, long cbso, long cbsi,
                     long gso, long gsi, int gcomp) {
    GP p;
    p.A = A; p.B = B; p.bias = bias; p.gate = gate; p.Cf = Cf; p.Cb = Cb;
    p.K2 = K2; p.lda = lda; p.ldb = ldb; p.ldcf = ldcf; p.ldcb = ldcb;
    p.alpha = alpha; p.accumulate = accum; p.zdiv = zdiv; p.gcomp = gcomp;
    p.aso = aso; p.asi = asi; p.bso = bso; p.bsi = bsi;
    p.cfso = cfso; p.cfsi = cfsi; p.cbso = cbso; p.cbsi = cbsi;
    p.gso = gso; p.gsi = gsi;
    dim3 grid(N / 128, M / 128, nz);
    gemm_k<<<grid, 256, 98304>>>(p);
}

// ================= straight convert: fp32 (R,C) -> fp16 split (R,2C) =================
__global__ void conv_k(const float* __restrict__ in, h16* __restrict__ out, int C, long n4) {
    long i = (long)blockIdx.x * 256 + threadIdx.x;
    if (i >= n4) return;
    long e = i * 4;
    long row = e / C;
    int c = (int)(e - row * C);
    float4 v = *(const float4*)(in + e);
    long ob = row * (long)(2 * C) + 64 * (c >> 5) + (c & 31);
    h16 h, l;
    h_split(v.x, h, l); out[ob] = h;     out[ob + 32] = l;
    h_split(v.y, h, l); out[ob + 1] = h; out[ob + 33] = l;
    h_split(v.z, h, l); out[ob + 2] = h; out[ob + 34] = l;
    h_split(v.w, h, l); out[ob + 3] = h; out[ob + 35] = l;
}

// ================= transpose convert: fp32 (R,C) -> fp16 split (C,2R), batched =================
__global__ void trconv_k(const float* __restrict__ in, h16* __restrict__ out,
                         int R, int C, long ibs, long obs) {
    __shared__ float tbuf[32][33];
    in += (long)blockIdx.z * ibs;
    out += (long)blockIdx.z * obs;
    int r0 = blockIdx.y * 32, c0 = blockIdx.x * 32;
    int tx = threadIdx.x, ty = threadIdx.y;
#pragma unroll
    for (int i = 0; i < 4; i++)
        tbuf[ty + i * 8][tx] = in[(long)(r0 + ty + i * 8) * C + c0 + tx];
    __syncthreads();
    int ld2 = 2 * R;
#pragma unroll
    for (int i = 0; i < 4; i++) {
        int oc = ty + i * 8;
        float v = tbuf[tx][oc];
        h16 h, l;
        h_split(v, h, l);
        long ob = (long)(c0 + oc) * ld2 + 2 * r0;
        out[ob + tx] = h;
        out[ob + 32 + tx] = l;
    }
}

// ================= gates + scores =================
__global__ void gates_scores_k(const float* __restrict__ x,
                               const float* __restrict__ Wg, const float* __restrict__ bg,
                               const float* __restrict__ Ws, const float* __restrict__ bs,
                               float* __restrict__ gates, float* __restrict__ scores) {
    int warp = threadIdx.x >> 5, lane = threadIdx.x & 31;
    long t = (long)blockIdx.x * 4 + warp;
    if (t >= N_TOK) return;
    const float* xr = x + t * HID_;
    float a0 = 0.f, a1 = 0.f, a2 = 0.f, a3 = 0.f;
    for (int d = lane; d < HID_; d += 32) {
        float xv = xr[d];
        a0 += xv * Wg[d * 3 + 0];
        a1 += xv * Wg[d * 3 + 1];
        a2 += xv * Wg[d * 3 + 2];
        a3 += xv * Ws[d];
    }
#pragma unroll
    for (int o = 16; o > 0; o >>= 1) {
        a0 += __shfl_down_sync(0xffffffffu, a0, o);
        a1 += __shfl_down_sync(0xffffffffu, a1, o);
        a2 += __shfl_down_sync(0xffffffffu, a2, o);
        a3 += __shfl_down_sync(0xffffffffu, a3, o);
    }
    if (lane == 0) {
        float g0 = 1.f / (1.f + expf(-(a0 + bg[0])));
        float g1 = 1.f / (1.f + expf(-(a1 + bg[1])));
        float g2 = 1.f / (1.f + expf(-(a2 + bg[2])));
        float s = g0 + g1 + g2 + 1e-6f;
        gates[t * 3 + 0] = g0 / s;
        gates[t * 3 + 1] = g1 / s;
        gates[t * 3 + 2] = g2 / s;
        scores[t] = a3 + bs[0];
    }
}

// ================= exact top-k =================
__device__ __forceinline__ bool before_f(float sa, int ia, float sb, int ib) {
    return (sa > sb) || (sa == sb && ia < ib);
}
__global__ void __launch_bounds__(512) topk_k(const float* __restrict__ scores, int* __restrict__ idx_out) {
    __shared__ float s[SEQ];
    __shared__ int id[SEQ];
    __shared__ int sel[KSEL];
    int b = blockIdx.x, tid = threadIdx.x;
    for (int i = tid; i < SEQ; i += 512) { s[i] = scores[(long)b * SEQ + i]; id[i] = i; }
    __syncthreads();
    for (int k = 2; k <= SEQ; k <<= 1)
        for (int j = k >> 1; j > 0; j >>= 1) {
            for (int i = tid; i < SEQ; i += 512) {
                int ixj = i ^ j;
                if (ixj > i) {
                    bool up = ((i & k) == 0);
                    bool ib = before_f(s[i], id[i], s[ixj], id[ixj]);
                    if (up ? !ib : ib) {
                        float ts = s[i]; s[i] = s[ixj]; s[ixj] = ts;
                        int ti = id[i]; id[i] = id[ixj]; id[ixj] = ti;
                    }
                }
            }
            __syncthreads();
        }
    if (tid < KSEL) sel[tid] = id[tid];
    __syncthreads();
    for (int k = 2; k <= KSEL; k <<= 1)
        for (int j = k >> 1; j > 0; j >>= 1) {
            int i = tid;
            if (i < KSEL) {
                int ixj = i ^ j;
                if (ixj > i) {
                    bool up = ((i & k) == 0);
                    if (up ? (sel[i] > sel[ixj]) : (sel[i] < sel[ixj])) {
                        int tt = sel[i]; sel[i] = sel[ixj]; sel[ixj] = tt;
                    }
                }
            }
            __syncthreads();
        }
    if (tid < KSEL) idx_out[b * KSEL + tid] = sel[tid];
}

// ================= gather =================
__global__ void gather_k(const h16* __restrict__ Qb, const h16* __restrict__ Kb,
                         const float* __restrict__ V, const int* __restrict__ idx,
                         h16* __restrict__ sq, h16* __restrict__ sk, float* __restrict__ sv) {
    int r = blockIdx.x;
    int b = r >> 9;
    long srow = (long)b * SEQ + idx[r];
    int tid = threadIdx.x;
    const uint4* q4 = (const uint4*)(Qb + srow * 2048);
    const uint4* k4 = (const uint4*)(Kb + srow * 2048);
    const uint4* v4 = (const uint4*)(V + srow * 1024);
    uint4* oq = (uint4*)(sq + (long)r * 2048);
    uint4* ok = (uint4*)(sk + (long)r * 2048);
    uint4* ov = (uint4*)(sv + (long)r * 1024);
    oq[tid] = q4[tid];
    ok[tid] = k4[tid];
    ov[tid] = v4[tid];
}

// ================= softmax (fp32 in, fp16 split out) =================
__global__ void softmax_k(const float* __restrict__ S, h16* __restrict__ Pb, int N) {
    __shared__ float buf[1024];
    __shared__ float red[256];
    long base = (long)blockIdx.x * N;
    long base2 = (long)blockIdx.x * 2 * N;
    int tid = threadIdx.x;
    float m = -1e30f;
    for (int i = tid; i < N; i += 256) { float xv = S[base + i]; buf[i] = xv; m = fmaxf(m, xv); }
    red[tid] = m; __syncthreads();
    for (int o = 128; o > 0; o >>= 1) { if (tid < o) red[tid] = fmaxf(red[tid], red[tid + o]); __syncthreads(); }
    m = red[0]; __syncthreads();
    float sum = 0.f;
    for (int i = tid; i < N; i += 256) { float e = expf(buf[i] - m); buf[i] = e; sum += e; }
    red[tid] = sum; __syncthreads();
    for (int o = 128; o > 0; o >>= 1) { if (tid < o) red[tid] += red[tid + o]; __syncthreads(); }
    float inv = 1.f / red[0];
    __syncthreads();
    for (int i = tid; i < N; i += 256) {
        float pv = buf[i] * inv;
        h16 h, l;
        h_split(pv, h, l);
        long ob = base2 + 64 * (i >> 5) + (i & 31);
        Pb[ob] = h;
        Pb[ob + 32] = l;
    }
}

// ================= residual + layernorm =================
__global__ void final_ln_k(const float* __restrict__ O, const float* __restrict__ x,
                           float* __restrict__ out) {
    long base = (long)blockIdx.x * HID_;
    int tid = threadIdx.x;
    float y[4];
    float s = 0.f, ss = 0.f;
#pragma unroll
    for (int i = 0; i < 4; i++) {
        int c = tid + i * 256;
        float v = 0.5f * (O[base + c] + x[base + c]);
        y[i] = v; s += v; ss += v * v;
    }
    __shared__ float rs[32], rss[32];
    int lane = tid & 31, warp = tid >> 5;
#pragma unroll
    for (int o = 16; o > 0; o >>= 1) {
        s += __shfl_down_sync(0xffffffffu, s, o);
        ss += __shfl_down_sync(0xffffffffu, ss, o);
    }
    if (lane == 0) { rs[warp] = s; rss[warp] = ss; }
    __syncthreads();
    if (warp == 0) {
        s = (lane < 8) ? rs[lane] : 0.f;
        ss = (lane < 8) ? rss[lane] : 0.f;
#pragma unroll
        for (int o = 4; o > 0; o >>= 1) {
            s += __shfl_down_sync(0xffffffffu, s, o);
            ss += __shfl_down_sync(0xffffffffu, ss, o);
        }
        if (lane == 0) { rs[0] = s; rss[0] = ss; }
    }
    __syncthreads();
    float mu = rs[0] * (1.f / HID_);
    float var = rss[0] * (1.f / HID_) - mu * mu;
    float inv = rsqrtf(var + 1e-6f);
#pragma unroll
    for (int i = 0; i < 4; i++) {
        int c = tid + i * 256;
        out[base + c] = (y[i] - mu) * inv;
    }
}

// ================= launch =================
extern "C" void kernel_launch(void* const* d_in, const int* in_sizes, int n_in,
                              void* d_out, int out_size) {
    const float* x  = (const float*)d_in[0];
    const float* Wq = (const float*)d_in[1];
    const float* bq = (const float*)d_in[2];
    const float* Wk = (const float*)d_in[3];
    const float* bk = (const float*)d_in[4];
    const float* Wv = (const float*)d_in[5];
    const float* bv = (const float*)d_in[6];
    const float* Wo = (const float*)d_in[7];
    const float* bo = (const float*)d_in[8];
    const float* Wg = (const float*)d_in[9];
    const float* bg = (const float*)d_in[10];
    const float* Wc = (const float*)d_in[11];
    const float* bc = (const float*)d_in[12];
    const float* Ws = (const float*)d_in[13];
    const float* bs = (const float*)d_in[14];

    cudaFuncSetAttribute(gemm_k, cudaFuncAttributeMaxDynamicSharedMemorySize, 98304);

    unsigned char* G; cudaGetSymbolAddress((void**)&G, g_scratch);
    int* idxp; cudaGetSymbolAddress((void**)&idxp, g_idx);

    h16* xb    = (h16*)(G + O_XB);
    h16* Qfb   = (h16*)(G + O_QFB);
    h16* Kfb   = (h16*)(G + O_KFB);
    float* Vf  = (float*)(G + O_VF);
    h16* tVfb  = (h16*)(G + O_TVFB);
    h16* compb = (h16*)(G + O_COMPB);
    h16* Qcb   = (h16*)(G + O_QCB);
    h16* Kcb   = (h16*)(G + O_KCB);
    float* Vc  = (float*)(G + O_VC);
    h16* tVcb  = (h16*)(G + O_TVCB);
    float* Sc  = (float*)(G + O_SC);
    h16* Scb   = (h16*)(G + O_SCB);
    h16* cPVb  = (h16*)(G + O_CPVB);
    h16* sQb   = (h16*)(G + O_SQB);
    h16* sKb   = (h16*)(G + O_SKB);
    float* sV  = (float*)(G + O_SV);
    h16* tSvb  = (h16*)(G + O_TSVB);
    float* Ss  = (float*)(G + O_SS);
    h16* Ssb   = (h16*)(G + O_SSB);
    h16* sPVb  = (h16*)(G + O_SPVB);
    float* Sw  = (float*)(G + O_SW);
    h16* Swb   = (h16*)(G + O_SWB);
    h16* wPVb  = (h16*)(G + O_WPVB);
    float* O   = (float*)(G + O_O);
    h16* tWq   = (h16*)(G + O_TWQ);
    h16* tWk   = (h16*)(G + O_TWK);
    h16* tWv   = (h16*)(G + O_TWV);
    h16* tWc   = (h16*)(G + O_TWC);
    h16* tWo0  = (h16*)(G + O_TWO0);
    h16* tWo1  = (h16*)(G + O_TWO1);
    h16* tWo2  = (h16*)(G + O_TWO2);
    float* gates  = (float*)(G + O_GATES);
    float* scores = (float*)(G + O_SCOR);
    float* outp = (float*)d_out;

    const float SCALE = 0.125f;
    dim3 trb(32, 8);

    // launches 1-5: conversions needed by the comp GEMM (launch 6 = ncu target)
    conv_k<<<(int)((N_TOK * HID_ / 4 + 255) / 256), 256>>>(x, xb, HID_, N_TOK * HID_ / 4);
    trconv_k<<<dim3(32, 32, 1), trb>>>(Wq, tWq, 1024, 1024, 0, 0);
    trconv_k<<<dim3(32, 32, 1), trb>>>(Wk, tWk, 1024, 1024, 0, 0);
    trconv_k<<<dim3(32, 32, 1), trb>>>(Wv, tWv, 1024, 1024, 0, 0);
    trconv_k<<<dim3(32, 128, 1), trb>>>(Wc, tWc, 4096, 1024, 0, 0);
    // launch 6: big K GEMM — comp = xblocks @ Wc
    run_gemm(xb, tWc, bc, nullptr, nullptr, compb, 4096, 1024, 8192, 8192, 8192, 0, 2048,
             1.f, 0, 1, 1, 0,0,0,0, 0,0, 0,0, 0,0, 0);

    trconv_k<<<dim3(32, 32, 1), trb>>>(Wo, tWo0, 1024, 1024, 0, 0);
    trconv_k<<<dim3(32, 32, 1), trb>>>(Wo + 1024L * 1024, tWo1, 1024, 1024, 0, 0);
    trconv_k<<<dim3(32, 32, 1), trb>>>(Wo + 2048L * 1024, tWo2, 1024, 1024, 0, 0);

    gates_scores_k<<<(int)(N_TOK / 4), 128>>>(x, Wg, bg, Ws, bs, gates, scores);
    topk_k<<<BATCH, 512>>>(scores, idxp);

    // full Q/K/V projections
    run_gemm(xb, tWq, bq, nullptr, nullptr, Qfb, (int)N_TOK, 1024, 2048, 2048, 2048, 0, 2048,
             1.f, 0, 1, 1, 0,0,0,0, 0,0, 0,0, 0,0, 0);
    run_gemm(xb, tWk, bk, nullptr, nullptr, Kfb, (int)N_TOK, 1024, 2048, 2048, 2048, 0, 2048,
             1.f, 0, 1, 1, 0,0,0,0, 0,0, 0,0, 0,0, 0);
    run_gemm(xb, tWv, bv, nullptr, Vf, nullptr, (int)N_TOK, 1024, 2048, 2048, 2048, 1024, 0,
             1.f, 0, 1, 1, 0,0,0,0, 0,0, 0,0, 0,0, 0);

    // compressed Q/K/V
    run_gemm(compb, tWq, bq, nullptr, nullptr, Qcb, 4096, 1024, 2048, 2048, 2048, 0, 2048,
             1.f, 0, 1, 1, 0,0,0,0, 0,0, 0,0, 0,0, 0);
    run_gemm(compb, tWk, bk, nullptr, nullptr, Kcb, 4096, 1024, 2048, 2048, 2048, 0, 2048,
             1.f, 0, 1, 1, 0,0,0,0, 0,0, 0,0, 0,0, 0);
    run_gemm(compb, tWv, bv, nullptr, Vc, nullptr, 4096, 1024, 2048, 2048, 2048, 1024, 0,
             1.f, 0, 1, 1, 0,0,0,0, 0,0, 0,0, 0,0, 0);

    // compressed attention
    run_gemm(Qcb, Kcb, nullptr, nullptr, Sc, nullptr, 1024, 1024, 2048, 2048, 2048, 1024, 0,
             SCALE, 0, BATCH, 1, 1024L*2048, 0, 1024L*2048, 0, 1024L*1024, 0, 0,0, 0,0, 0);
    softmax_k<<<BATCH * 1024, 256>>>(Sc, Scb, 1024);
    trconv_k<<<dim3(32, 32, BATCH), trb>>>(Vc, tVcb, 1024, 1024, 1024L*1024, 1024L*2048);
    run_gemm(Scb, tVcb, nullptr, gates, nullptr, cPVb, 1024, 1024, 2048, 2048, 2048, 0, 2048,
             1.f, 0, BATCH, 1, 1024L*2048, 0, 1024L*2048, 0, 0,0, 1024L*2048, 0,
             (long)SEQ*3, 0, 0);

    // selected branch
    gather_k<<<BATCH * KSEL, 256>>>(Qfb, Kfb, Vf, idxp, sQb, sKb, sV);
    run_gemm(sQb, sKb, nullptr, nullptr, Ss, nullptr, 512, 512, 2048, 2048, 2048, 512, 0,
             SCALE, 0, BATCH, 1, 512L*2048, 0, 512L*2048, 0, 512L*512, 0, 0,0, 0,0, 0);
    softmax_k<<<BATCH * 512, 256>>>(Ss, Ssb, 512);
    trconv_k<<<dim3(32, 16, BATCH), trb>>>(sV, tSvb, 512, 1024, 512L*1024, 1024L*1024);
    run_gemm(Ssb, tSvb, nullptr, gates, nullptr, sPVb, 512, 1024, 1024, 1024, 1024, 0, 2048,
             1.f, 0, BATCH, 1, 512L*1024, 0, 1024L*1024, 0, 0,0, 512L*2048, 0,
             (long)SEQ*3, 0, 1);

    // window branch
    trconv_k<<<dim3(32, 128, BATCH), trb>>>(Vf, tVfb, 4096, 1024, 4096L*1024, 1024L*8192);
    run_gemm(Qfb, Kfb, nullptr, nullptr, Sw, nullptr, WIN, WIN, 2048, 2048, 2048, WIN, 0,
             SCALE, 0, BATCH * NWIN, NWIN,
             (long)SEQ*2048, 128L*2048, (long)SEQ*2048, 128L*2048,
             (long)NWIN*WIN*WIN, (long)WIN*WIN, 0,0, 0,0, 0);
    softmax_k<<<BATCH * NWIN * WIN, 256>>>(Sw, Swb, WIN);
    run_gemm(Swb, tVfb, nullptr, gates, nullptr, wPVb, WIN, 1024, 512, 512, 8192, 0, 2048,
             1.f, 0, BATCH * NWIN, NWIN,
             (long)NWIN*WIN*512, (long)WIN*512,
             1024L*8192, 256,
             0,0, (long)SEQ*2048, (long)WIN*2048,
             (long)SEQ*3, (long)WIN*3, 2);

    // output projection
    run_gemm(wPVb, tWo2, bo, nullptr, O, nullptr, (int)N_TOK, 1024, 2048, 2048, 2048, 1024, 0,
             1.f, 0, 1, 1, 0,0,0,0, 0,0, 0,0, 0,0, 0);
    run_gemm(cPVb, tWo0, nullptr, nullptr, O, nullptr, 1024, 1024, 2048, 2048, 2048, 1024, 0,
             1.f, 1, BATCH, 1, 1024L*2048, 0, 0, 0, (long)SEQ*1024, 0, 0,0, 0,0, 0);
    run_gemm(sPVb, tWo1, nullptr, nullptr, O, nullptr, 512, 1024, 2048, 2048, 2048, 1024, 0,
             1.f, 1, BATCH, 1, 512L*2048, 0, 0, 0, (long)SEQ*1024, 0, 0,0, 0,0, 0);

    // residual + layernorm
    final_ln_k<<<(int)N_TOK, 256>>>(O, x, outp);
}

// round 11
// speedup vs baseline: 1.5057x; 1.5057x over previous
#include <cuda_runtime.h>
#include <cuda_fp16.h>
#include <math.h>
#include <stdint.h>

// ---------------- problem constants ----------------
#define BATCH 4
#define SEQ   4096
#define HID_  1024
#define LC    1024
#define KSEL  512
#define WIN   256
#define NWIN  16

static const long N_TOK = (long)BATCH * SEQ;

// ---------------- scratch layout (bytes) ----------------
// fp16 split matrices: rows of length 2*K; per 32-orig-col block b,
// cols 64b..64b+31 = hi, 64b+32..64b+63 = lo. B-side GEMM reads hi only.
constexpr long O_XB    = 0;
constexpr long O_QFB   = O_XB    + 67108864L;
constexpr long O_KFB   = O_QFB   + 67108864L;
constexpr long O_VF    = O_KFB   + 67108864L;
constexpr long O_TVFB  = O_VF    + 67108864L;
constexpr long O_COMPB = O_TVFB  + 67108864L;
constexpr long O_QCB   = O_COMPB + 16777216L;
constexpr long O_KCB   = O_QCB   + 16777216L;
constexpr long O_VC    = O_KCB   + 16777216L;
constexpr long O_TVCB  = O_VC    + 16777216L;
constexpr long O_SC    = O_TVCB  + 16777216L;
constexpr long O_SCB   = O_SC    + 16777216L;
constexpr long O_CPVB  = O_SCB   + 16777216L;
constexpr long O_SQB   = O_CPVB  + 16777216L;
constexpr long O_SKB   = O_SQB   + 8388608L;
constexpr long O_SV    = O_SKB   + 8388608L;
constexpr long O_TSVB  = O_SV    + 8388608L;
constexpr long O_SS    = O_TSVB  + 8388608L;
constexpr long O_SSB   = O_SS    + 4194304L;
constexpr long O_SPVB  = O_SSB   + 4194304L;
constexpr long O_SW    = O_SPVB  + 8388608L;
constexpr long O_SWB   = O_SW    + 16777216L;
constexpr long O_WPVB  = O_SWB   + 16777216L;
constexpr long O_O     = O_WPVB  + 67108864L;
constexpr long O_TWQ   = O_O     + 67108864L;
constexpr long O_TWK   = O_TWQ   + 4194304L;
constexpr long O_TWV   = O_TWK   + 4194304L;
constexpr long O_TWC   = O_TWV   + 4194304L;
constexpr long O_TWO0  = O_TWC   + 16777216L;
constexpr long O_TWO1  = O_TWO0  + 4194304L;
constexpr long O_TWO2  = O_TWO1  + 4194304L;
constexpr long O_GATES = O_TWO2  + 4194304L;
constexpr long O_SCOR  = O_GATES + 196608L;
constexpr long TOTALB  = O_SCOR  + 65536L;

__device__ __align__(1024) unsigned char g_scratch[TOTALB];
__device__ int g_idx[BATCH * KSEL];

typedef __half h16;

// ================= PTX helpers =================
__device__ __forceinline__ uint32_t smem_u32(const void* p) {
    uint32_t a;
    asm("{ .reg .u64 t; cvta.to.shared.u64 t, %1; cvt.u32.u64 %0, t; }" : "=r"(a) : "l"(p));
    return a;
}
__device__ __forceinline__ void cp16(uint32_t dst, const void* src) {
    asm volatile("cp.async.cg.shared.global [%0], [%1], 16;" :: "r"(dst), "l"(src));
}
#define CP_COMMIT() asm volatile("cp.async.commit_group;" ::: "memory")
#define CP_WAIT1()  asm volatile("cp.async.wait_group 1;" ::: "memory")

__device__ __forceinline__ void ldm4(uint32_t* r, uint32_t addr) {
    asm volatile("ldmatrix.sync.aligned.m8n8.x4.shared.b16 {%0,%1,%2,%3}, [%4];"
        : "=r"(r[0]), "=r"(r[1]), "=r"(r[2]), "=r"(r[3]) : "r"(addr));
}
__device__ __forceinline__ void mma16816(float* d, const uint32_t* a, const uint32_t* b) {
    asm volatile(
        "mma.sync.aligned.m16n8k16.row.col.f32.f16.f16.f32 "
        "{%0,%1,%2,%3}, {%4,%5,%6,%7}, {%8,%9}, {%0,%1,%2,%3};"
        : "+f"(d[0]), "+f"(d[1]), "+f"(d[2]), "+f"(d[3])
        : "r"(a[0]), "r"(a[1]), "r"(a[2]), "r"(a[3]), "r"(b[0]), "r"(b[1]));
}
__device__ __forceinline__ void h_split(float v, h16& h, h16& l) {
    h = __float2half_rn(v);
    l = __float2half_rn(v - __half2float(h));
}

// ================= pipelined HMMA GEMM (fp16 split A x fp16-hi B) =================
// C[M,N] = alpha * A·Bhi^T (+bias)(accum into Cf)(*gate(row))
// Tile 128x128, chunk 32 orig-k (=64 split cols).
// 3-stage cp.async ring (24KB stages), two barriers per chunk (R5-proven skeleton).
#define STAGE_B 24576
struct GP {
    const h16 *A, *B;
    const float *bias, *gate;
    float *Cf; h16 *Cb;
    int K2, lda, ldb, ldcf, ldcb;
    float alpha;
    int accumulate, zdiv, gcomp;
    long aso, asi, bso, bsi, cfso, cfsi, cbso, cbsi, gso, gsi;
};

__device__ __forceinline__ void stage_load(uint32_t smb, int s, const h16* A, const h16* B,
                                           int lda, int ldb, int k2off, int tid) {
    uint32_t sa = smb + s * STAGE_B;
    uint32_t sb2 = sa + 16384;
#pragma unroll
    for (int i = 0; i < 4; i++) {            // A: 128 rows x 8 segs (128B rows, hi+lo)
        int idx = tid + i * 256;
        int row = idx >> 3, seg = idx & 7;
        cp16(sa + row * 128 + ((seg ^ (row & 7)) << 4), A + (long)row * lda + k2off + seg * 8);
    }
#pragma unroll
    for (int i = 0; i < 2; i++) {            // B hi: 128 rows x 4 segs (64B rows)
        int idx = tid + i * 256;
        int row = idx >> 2, seg = idx & 3;
        cp16(sb2 + row * 64 + ((seg ^ ((row >> 1) & 3)) << 4),
             B + (long)row * ldb + k2off + seg * 8);
    }
    CP_COMMIT();
}

__device__ __forceinline__ uint32_t swzA(uint32_t base, int r, int cb) {
    return base + r * 128 + ((((cb >> 4) ^ (r & 7))) << 4);
}

__global__ void __launch_bounds__(256, 2) gemm_k(GP p) {
    extern __shared__ __align__(1024) char sm[];
    uint32_t smb = smem_u32(sm);
    const int tid = threadIdx.x, lane = tid & 31, wid = tid >> 5;
    const int wm = wid & 3, wn = wid >> 2;

    const long zo = blockIdx.z / p.zdiv, zi = blockIdx.z - zo * (long)p.zdiv;
    const h16* A = p.A + zo * p.aso + zi * p.asi + (long)blockIdx.y * 128 * p.lda;
    const h16* B = p.B + zo * p.bso + zi * p.bsi + (long)blockIdx.x * 128 * p.ldb;

    float acc[2][8][4];
#pragma unroll
    for (int mt = 0; mt < 2; mt++)
#pragma unroll
        for (int nt = 0; nt < 8; nt++)
#pragma unroll
            for (int r = 0; r < 4; r++) acc[mt][nt][r] = 0.f;

    const int nch = p.K2 >> 6;
    stage_load(smb, 0, A, B, p.lda, p.ldb, 0, tid);
    stage_load(smb, 1, A, B, p.lda, p.ldb, 64, tid);

    for (int c = 0; c < nch; c++) {
        CP_WAIT1();
        __syncthreads();
        if (c + 2 < nch) stage_load(smb, (c + 2) % 3, A, B, p.lda, p.ldb, (c + 2) * 64, tid);
        else CP_COMMIT();

        uint32_t sa = smb + (c % 3) * STAGE_B, sbB = sa + 16384;
#pragma unroll
        for (int ks = 0; ks < 2; ks++) {
            uint32_t aH[2][4], aL[2][4];
            int ar = wm * 32 + (lane & 15);
            int acb = ks * 32 + ((lane >> 4) << 4);
#pragma unroll
            for (int mt = 0; mt < 2; mt++) {
                ldm4(aH[mt], swzA(sa, ar + mt * 16, acb));
                ldm4(aL[mt], swzA(sa, ar + mt * 16, acb + 64));
            }
            int seg = ks * 2 + ((lane >> 3) & 1);
#pragma unroll
            for (int nb = 0; nb < 4; nb++) {
                int brow = wn * 64 + nb * 16 + (lane & 7) + ((lane >> 4) << 3);
                uint32_t h4[4];
                ldm4(h4, sbB + brow * 64 + ((seg ^ ((brow >> 1) & 3)) << 4));
#pragma unroll
                for (int sub = 0; sub < 2; sub++) {
                    int nt = nb * 2 + sub;
#pragma unroll
                    for (int mt = 0; mt < 2; mt++) {
                        mma16816(acc[mt][nt], aH[mt], h4 + sub * 2);
                        mma16816(acc[mt][nt], aL[mt], h4 + sub * 2);
                    }
                }
            }
        }
        __syncthreads();
    }

    // ---- epilogue ----
    const float* gb = p.gate ? (p.gate + zo * p.gso + zi * p.gsi) : nullptr;
    float* Cf = p.Cf ? (p.Cf + zo * p.cfso + zi * p.cfsi) : nullptr;
    h16* Cb = p.Cb ? (p.Cb + zo * p.cbso + zi * p.cbsi) : nullptr;
    const long rowBase = (long)blockIdx.y * 128 + wm * 32;
    const long colBase = (long)blockIdx.x * 128 + wn * 64;
    const int g = lane >> 2, t = lane & 3;
#pragma unroll
    for (int mt = 0; mt < 2; mt++) {
        long r0 = rowBase + mt * 16 + g, r1 = r0 + 8;
        float gv0 = gb ? gb[r0 * 3 + p.gcomp] : 1.f;
        float gv1 = gb ? gb[r1 * 3 + p.gcomp] : 1.f;
#pragma unroll
        for (int nt = 0; nt < 8; nt++) {
            long c = colBase + nt * 8 + t * 2;
            float b0 = p.bias ? p.bias[c] : 0.f;
            float b1 = p.bias ? p.bias[c + 1] : 0.f;
            float* d = acc[mt][nt];
            float v0 = p.alpha * d[0] + b0, v1 = p.alpha * d[1] + b1;
            float v2 = p.alpha * d[2] + b0, v3 = p.alpha * d[3] + b1;
            if (Cf) {
                long o0 = r0 * (long)p.ldcf + c, o1 = r1 * (long)p.ldcf + c;
                if (p.accumulate) { v0 += Cf[o0]; v1 += Cf[o0 + 1]; v2 += Cf[o1]; v3 += Cf[o1 + 1]; }
                v0 *= gv0; v1 *= gv0; v2 *= gv1; v3 *= gv1;
                *(float2*)(Cf + o0) = make_float2(v0, v1);
                *(float2*)(Cf + o1) = make_float2(v2, v3);
            } else {
                v0 *= gv0; v1 *= gv0; v2 *= gv1; v3 *= gv1;
            }
            if (Cb) {
                int oc = (int)(64 * (c >> 5) + (c & 31));
                h16 h, l;
                __half2 hp, lp;
                h_split(v0, h, l); hp.x = h; lp.x = l;
                h_split(v1, h, l); hp.y = h; lp.y = l;
                *(__half2*)(Cb + r0 * (long)p.ldcb + oc) = hp;
                *(__half2*)(Cb + r0 * (long)p.ldcb + oc + 32) = lp;
                h_split(v2, h, l); hp.x = h; lp.x = l;
                h_split(v3, h, l); hp.y = h; lp.y = l;
                *(__half2*)(Cb + r1 * (long)p.ldcb + oc) = hp;
                *(__half2*)(Cb + r1 * (long)p.ldcb + oc + 32) = lp;
            }
        }
    }
}

static void run_gemm(const h16* A, const h16* B, const float* bias, const float* gate,
                     float* Cf, h16* Cb, int M, int N, int K2,
                     int lda, int ldb, int ldcf, int ldcb, float alpha,
                     int accum, int nz, int zdiv,
                     long aso, long asi, long bso, long bsi,
                     long cfso, long cfsi, long cbso, long cbsi,
                     long gso, long gsi, int gcomp) {
    GP p;
    p.A = A; p.B = B; p.bias = bias; p.gate = gate; p.Cf = Cf; p.Cb = Cb;
    p.K2 = K2; p.lda = lda; p.ldb = ldb; p.ldcf = ldcf; p.ldcb = ldcb;
    p.alpha = alpha; p.accumulate = accum; p.zdiv = zdiv; p.gcomp = gcomp;
    p.aso = aso; p.asi = asi; p.bso = bso; p.bsi = bsi;
    p.cfso = cfso; p.cfsi = cfsi; p.cbso = cbso; p.cbsi = cbsi;
    p.gso = gso; p.gsi = gsi;
    dim3 grid(N / 128, M / 128, nz);
    gemm_k<<<grid, 256, 3 * STAGE_B>>>(p);
}

// ================= straight convert: fp32 (R,C) -> fp16 split (R,2C) =================
__global__ void conv_k(const float* __restrict__ in, h16* __restrict__ out, int C, long n4) {
    long i = (long)blockIdx.x * 256 + threadIdx.x;
    if (i >= n4) return;
    long e = i * 4;
    long row = e / C;
    int c = (int)(e - row * C);
    float4 v = *(const float4*)(in + e);
    long ob = row * (long)(2 * C) + 64 * (c >> 5) + (c & 31);
    h16 h, l;
    h_split(v.x, h, l); out[ob] = h;     out[ob + 32] = l;
    h_split(v.y, h, l); out[ob + 1] = h; out[ob + 33] = l;
    h_split(v.z, h, l); out[ob + 2] = h; out[ob + 34] = l;
    h_split(v.w, h, l); out[ob + 3] = h; out[ob + 35] = l;
}

// ================= transpose convert: fp32 (R,C) -> fp16 split (C,2R), batched =================
__global__ void trconv_k(const float* __restrict__ in, h16* __restrict__ out,
                         int R, int C, long ibs, long obs) {
    __shared__ float tbuf[32][33];
    in += (long)blockIdx.z * ibs;
    out += (long)blockIdx.z * obs;
    int r0 = blockIdx.y * 32, c0 = blockIdx.x * 32;
    int tx = threadIdx.x, ty = threadIdx.y;
#pragma unroll
    for (int i = 0; i < 4; i++)
        tbuf[ty + i * 8][tx] = in[(long)(r0 + ty + i * 8) * C + c0 + tx];
    __syncthreads();
    int ld2 = 2 * R;
#pragma unroll
    for (int i = 0; i < 4; i++) {
        int oc = ty + i * 8;
        float v = tbuf[tx][oc];
        h16 h, l;
        h_split(v, h, l);
        long ob = (long)(c0 + oc) * ld2 + 2 * r0;
        out[ob + tx] = h;
        out[ob + 32 + tx] = l;
    }
}

// ================= gates + scores =================
__global__ void gates_scores_k(const float* __restrict__ x,
                               const float* __restrict__ Wg, const float* __restrict__ bg,
                               const float* __restrict__ Ws, const float* __restrict__ bs,
                               float* __restrict__ gates, float* __restrict__ scores) {
    int warp = threadIdx.x >> 5, lane = threadIdx.x & 31;
    long t = (long)blockIdx.x * 4 + warp;
    if (t >= N_TOK) return;
    const float* xr = x + t * HID_;
    float a0 = 0.f, a1 = 0.f, a2 = 0.f, a3 = 0.f;
    for (int d = lane; d < HID_; d += 32) {
        float xv = xr[d];
        a0 += xv * Wg[d * 3 + 0];
        a1 += xv * Wg[d * 3 + 1];
        a2 += xv * Wg[d * 3 + 2];
        a3 += xv * Ws[d];
    }
#pragma unroll
    for (int o = 16; o > 0; o >>= 1) {
        a0 += __shfl_down_sync(0xffffffffu, a0, o);
        a1 += __shfl_down_sync(0xffffffffu, a1, o);
        a2 += __shfl_down_sync(0xffffffffu, a2, o);
        a3 += __shfl_down_sync(0xffffffffu, a3, o);
    }
    if (lane == 0) {
        float g0 = 1.f / (1.f + expf(-(a0 + bg[0])));
        float g1 = 1.f / (1.f + expf(-(a1 + bg[1])));
        float g2 = 1.f / (1.f + expf(-(a2 + bg[2])));
        float s = g0 + g1 + g2 + 1e-6f;
        gates[t * 3 + 0] = g0 / s;
        gates[t * 3 + 1] = g1 / s;
        gates[t * 3 + 2] = g2 / s;
        scores[t] = a3 + bs[0];
    }
}

// ================= exact top-k =================
__device__ __forceinline__ bool before_f(float sa, int ia, float sb, int ib) {
    return (sa > sb) || (sa == sb && ia < ib);
}
__global__ void __launch_bounds__(512) topk_k(const float* __restrict__ scores, int* __restrict__ idx_out) {
    __shared__ float s[SEQ];
    __shared__ int id[SEQ];
    __shared__ int sel[KSEL];
    int b = blockIdx.x, tid = threadIdx.x;
    for (int i = tid; i < SEQ; i += 512) { s[i] = scores[(long)b * SEQ + i]; id[i] = i; }
    __syncthreads();
    for (int k = 2; k <= SEQ; k <<= 1)
        for (int j = k >> 1; j > 0; j >>= 1) {
            for (int i = tid; i < SEQ; i += 512) {
                int ixj = i ^ j;
                if (ixj > i) {
                    bool up = ((i & k) == 0);
                    bool ib = before_f(s[i], id[i], s[ixj], id[ixj]);
                    if (up ? !ib : ib) {
                        float ts = s[i]; s[i] = s[ixj]; s[ixj] = ts;
                        int ti = id[i]; id[i] = id[ixj]; id[ixj] = ti;
                    }
                }
            }
            __syncthreads();
        }
    if (tid < KSEL) sel[tid] = id[tid];
    __syncthreads();
    for (int k = 2; k <= KSEL; k <<= 1)
        for (int j = k >> 1; j > 0; j >>= 1) {
            int i = tid;
            if (i < KSEL) {
                int ixj = i ^ j;
                if (ixj > i) {
                    bool up = ((i & k) == 0);
                    if (up ? (sel[i] > sel[ixj]) : (sel[i] < sel[ixj])) {
                        int tt = sel[i]; sel[i] = sel[ixj]; sel[ixj] = tt;
                    }
                }
            }
            __syncthreads();
        }
    if (tid < KSEL) idx_out[b * KSEL + tid] = sel[tid];
}

// ================= gather =================
__global__ void gather_k(const h16* __restrict__ Qb, const h16* __restrict__ Kb,
                         const float* __restrict__ V, const int* __restrict__ idx,
                         h16* __restrict__ sq, h16* __restrict__ sk, float* __restrict__ sv) {
    int r = blockIdx.x;
    int b = r >> 9;
    long srow = (long)b * SEQ + idx[r];
    int tid = threadIdx.x;
    const uint4* q4 = (const uint4*)(Qb + srow * 2048);
    const uint4* k4 = (const uint4*)(Kb + srow * 2048);
    const uint4* v4 = (const uint4*)(V + srow * 1024);
    uint4* oq = (uint4*)(sq + (long)r * 2048);
    uint4* ok = (uint4*)(sk + (long)r * 2048);
    uint4* ov = (uint4*)(sv + (long)r * 1024);
    oq[tid] = q4[tid];
    ok[tid] = k4[tid];
    ov[tid] = v4[tid];
}

// ================= softmax (fp32 in, fp16 split out) =================
__global__ void softmax_k(const float* __restrict__ S, h16* __restrict__ Pb, int N) {
    __shared__ float buf[1024];
    __shared__ float red[256];
    long base = (long)blockIdx.x * N;
    long base2 = (long)blockIdx.x * 2 * N;
    int tid = threadIdx.x;
    float m = -1e30f;
    for (int i = tid; i < N; i += 256) { float xv = S[base + i]; buf[i] = xv; m = fmaxf(m, xv); }
    red[tid] = m; __syncthreads();
    for (int o = 128; o > 0; o >>= 1) { if (tid < o) red[tid] = fmaxf(red[tid], red[tid + o]); __syncthreads(); }
    m = red[0]; __syncthreads();
    float sum = 0.f;
    for (int i = tid; i < N; i += 256) { float e = expf(buf[i] - m); buf[i] = e; sum += e; }
    red[tid] = sum; __syncthreads();
    for (int o = 128; o > 0; o >>= 1) { if (tid < o) red[tid] += red[tid + o]; __syncthreads(); }
    float inv = 1.f / red[0];
    __syncthreads();
    for (int i = tid; i < N; i += 256) {
        float pv = buf[i] * inv;
        h16 h, l;
        h_split(pv, h, l);
        long ob = base2 + 64 * (i >> 5) + (i & 31);
        Pb[ob] = h;
        Pb[ob + 32] = l;
    }
}

// ================= residual + layernorm =================
__global__ void final_ln_k(const float* __restrict__ O, const float* __restrict__ x,
                           float* __restrict__ out) {
    long base = (long)blockIdx.x * HID_;
    int tid = threadIdx.x;
    float y[4];
    float s = 0.f, ss = 0.f;
#pragma unroll
    for (int i = 0; i < 4; i++) {
        int c = tid + i * 256;
        float v = 0.5f * (O[base + c] + x[base + c]);
        y[i] = v; s += v; ss += v * v;
    }
    __shared__ float rs[32], rss[32];
    int lane = tid & 31, warp = tid >> 5;
#pragma unroll
    for (int o = 16; o > 0; o >>= 1) {
        s += __shfl_down_sync(0xffffffffu, s, o);
        ss += __shfl_down_sync(0xffffffffu, ss, o);
    }
    if (lane == 0) { rs[warp] = s; rss[warp] = ss; }
    __syncthreads();
    if (warp == 0) {
        s = (lane < 8) ? rs[lane] : 0.f;
        ss = (lane < 8) ? rss[lane] : 0.f;
#pragma unroll
        for (int o = 4; o > 0; o >>= 1) {
            s += __shfl_down_sync(0xffffffffu, s, o);
            ss += __shfl_down_sync(0xffffffffu, ss, o);
        }
        if (lane == 0) { rs[0] = s; rss[0] = ss; }
    }
    __syncthreads();
    float mu = rs[0] * (1.f / HID_);
    float var = rss[0] * (1.f / HID_) - mu * mu;
    float inv = rsqrtf(var + 1e-6f);
#pragma unroll
    for (int i = 0; i < 4; i++) {
        int c = tid + i * 256;
        out[base + c] = (y[i] - mu) * inv;
    }
}

// ================= launch =================
extern "C" void kernel_launch(void* const* d_in, const int* in_sizes, int n_in,
                              void* d_out, int out_size) {
    const float* x  = (const float*)d_in[0];
    const float* Wq = (const float*)d_in[1];
    const float* bq = (const float*)d_in[2];
    const float* Wk = (const float*)d_in[3];
    const float* bk = (const float*)d_in[4];
    const float* Wv = (const float*)d_in[5];
    const float* bv = (const float*)d_in[6];
    const float* Wo = (const float*)d_in[7];
    const float* bo = (const float*)d_in[8];
    const float* Wg = (const float*)d_in[9];
    const float* bg = (const float*)d_in[10];
    const float* Wc = (const float*)d_in[11];
    const float* bc = (const float*)d_in[12];
    const float* Ws = (const float*)d_in[13];
    const float* bs = (const float*)d_in[14];

    cudaFuncSetAttribute(gemm_k, cudaFuncAttributeMaxDynamicSharedMemorySize, 3 * STAGE_B);

    unsigned char* G; cudaGetSymbolAddress((void**)&G, g_scratch);
    int* idxp; cudaGetSymbolAddress((void**)&idxp, g_idx);

    h16* xb    = (h16*)(G + O_XB);
    h16* Qfb   = (h16*)(G + O_QFB);
    h16* Kfb   = (h16*)(G + O_KFB);
    float* Vf  = (float*)(G + O_VF);
    h16* tVfb  = (h16*)(G + O_TVFB);
    h16* compb = (h16*)(G + O_COMPB);
    h16* Qcb   = (h16*)(G + O_QCB);
    h16* Kcb   = (h16*)(G + O_KCB);
    float* Vc  = (float*)(G + O_VC);
    h16* tVcb  = (h16*)(G + O_TVCB);
    float* Sc  = (float*)(G + O_SC);
    h16* Scb   = (h16*)(G + O_SCB);
    h16* cPVb  = (h16*)(G + O_CPVB);
    h16* sQb   = (h16*)(G + O_SQB);
    h16* sKb   = (h16*)(G + O_SKB);
    float* sV  = (float*)(G + O_SV);
    h16* tSvb  = (h16*)(G + O_TSVB);
    float* Ss  = (float*)(G + O_SS);
    h16* Ssb   = (h16*)(G + O_SSB);
    h16* sPVb  = (h16*)(G + O_SPVB);
    float* Sw  = (float*)(G + O_SW);
    h16* Swb   = (h16*)(G + O_SWB);
    h16* wPVb  = (h16*)(G + O_WPVB);
    float* O   = (float*)(G + O_O);
    h16* tWq   = (h16*)(G + O_TWQ);
    h16* tWk   = (h16*)(G + O_TWK);
    h16* tWv   = (h16*)(G + O_TWV);
    h16* tWc   = (h16*)(G + O_TWC);
    h16* tWo0  = (h16*)(G + O_TWO0);
    h16* tWo1  = (h16*)(G + O_TWO1);
    h16* tWo2  = (h16*)(G + O_TWO2);
    float* gates  = (float*)(G + O_GATES);
    float* scores = (float*)(G + O_SCOR);
    float* outp = (float*)d_out;

    const float SCALE = 0.125f;
    dim3 trb(32, 8);

    // launches 1-5, then launch 6 = big comp GEMM (ncu -s 5 -c 1 target)
    conv_k<<<(int)((N_TOK * HID_ / 4 + 255) / 256), 256>>>(x, xb, HID_, N_TOK * HID_ / 4);
    trconv_k<<<dim3(32, 32, 1), trb>>>(Wq, tWq, 1024, 1024, 0, 0);
    trconv_k<<<dim3(32, 32, 1), trb>>>(Wk, tWk, 1024, 1024, 0, 0);
    trconv_k<<<dim3(32, 32, 1), trb>>>(Wv, tWv, 1024, 1024, 0, 0);
    trconv_k<<<dim3(32, 128, 1), trb>>>(Wc, tWc, 4096, 1024, 0, 0);
    run_gemm(xb, tWc, bc, nullptr, nullptr, compb, 4096, 1024, 8192, 8192, 8192, 0, 2048,
             1.f, 0, 1, 1, 0,0,0,0, 0,0, 0,0, 0,0, 0);

    trconv_k<<<dim3(32, 32, 1), trb>>>(Wo, tWo0, 1024, 1024, 0, 0);
    trconv_k<<<dim3(32, 32, 1), trb>>>(Wo + 1024L * 1024, tWo1, 1024, 1024, 0, 0);
    trconv_k<<<dim3(32, 32, 1), trb>>>(Wo + 2048L * 1024, tWo2, 1024, 1024, 0, 0);

    gates_scores_k<<<(int)(N_TOK / 4), 128>>>(x, Wg, bg, Ws, bs, gates, scores);
    topk_k<<<BATCH, 512>>>(scores, idxp);

    // full Q/K/V projections
    run_gemm(xb, tWq, bq, nullptr, nullptr, Qfb, (int)N_TOK, 1024, 2048, 2048, 2048, 0, 2048,
             1.f, 0, 1, 1, 0,0,0,0, 0,0, 0,0, 0,0, 0);
    run_gemm(xb, tWk, bk, nullptr, nullptr, Kfb, (int)N_TOK, 1024, 2048, 2048, 2048, 0, 2048,
             1.f, 0, 1, 1, 0,0,0,0, 0,0, 0,0, 0,0, 0);
    run_gemm(xb, tWv, bv, nullptr, Vf, nullptr, (int)N_TOK, 1024, 2048, 2048, 2048, 1024, 0,
             1.f, 0, 1, 1, 0,0,0,0, 0,0, 0,0, 0,0, 0);

    // compressed Q/K/V
    run_gemm(compb, tWq, bq, nullptr, nullptr, Qcb, 4096, 1024, 2048, 2048, 2048, 0, 2048,
             1.f, 0, 1, 1, 0,0,0,0, 0,0, 0,0, 0,0, 0);
    run_gemm(compb, tWk, bk, nullptr, nullptr, Kcb, 4096, 1024, 2048, 2048, 2048, 0, 2048,
             1.f, 0, 1, 1, 0,0,0,0, 0,0, 0,0, 0,0, 0);
    run_gemm(compb, tWv, bv, nullptr, Vc, nullptr, 4096, 1024, 2048, 2048, 2048, 1024, 0,
             1.f, 0, 1, 1, 0,0,0,0, 0,0, 0,0, 0,0, 0);

    // compressed attention
    run_gemm(Qcb, Kcb, nullptr, nullptr, Sc, nullptr, 1024, 1024, 2048, 2048, 2048, 1024, 0,
             SCALE, 0, BATCH, 1, 1024L*2048, 0, 1024L*2048, 0, 1024L*1024, 0, 0,0, 0,0, 0);
    softmax_k<<<BATCH * 1024, 256>>>(Sc, Scb, 1024);
    trconv_k<<<dim3(32, 32, BATCH), trb>>>(Vc, tVcb, 1024, 1024, 1024L*1024, 1024L*2048);
    run_gemm(Scb, tVcb, nullptr, gates, nullptr, cPVb, 1024, 1024, 2048, 2048, 2048, 0, 2048,
             1.f, 0, BATCH, 1, 1024L*2048, 0, 1024L*2048, 0, 0,0, 1024L*2048, 0,
             (long)SEQ*3, 0, 0);

    // selected branch
    gather_k<<<BATCH * KSEL, 256>>>(Qfb, Kfb, Vf, idxp, sQb, sKb, sV);
    run_gemm(sQb, sKb, nullptr, nullptr, Ss, nullptr, 512, 512, 2048, 2048, 2048, 512, 0,
             SCALE, 0, BATCH, 1, 512L*2048, 0, 512L*2048, 0, 512L*512, 0, 0,0, 0,0, 0);
    softmax_k<<<BATCH * 512, 256>>>(Ss, Ssb, 512);
    trconv_k<<<dim3(32, 16, BATCH), trb>>>(sV, tSvb, 512, 1024, 512L*1024, 1024L*1024);
    run_gemm(Ssb, tSvb, nullptr, gates, nullptr, sPVb, 512, 1024, 1024, 1024, 1024, 0, 2048,
             1.f, 0, BATCH, 1, 512L*1024, 0, 1024L*1024, 0, 0,0, 512L*2048, 0,
             (long)SEQ*3, 0, 1);

    // window branch
    trconv_k<<<dim3(32, 128, BATCH), trb>>>(Vf, tVfb, 4096, 1024, 4096L*1024, 1024L*8192);
    run_gemm(Qfb, Kfb, nullptr, nullptr, Sw, nullptr, WIN, WIN, 2048, 2048, 2048, WIN, 0,
             SCALE, 0, BATCH * NWIN, NWIN,
             (long)SEQ*2048, 128L*2048, (long)SEQ*2048, 128L*2048,
             (long)NWIN*WIN*WIN, (long)WIN*WIN, 0,0, 0,0, 0);
    softmax_k<<<BATCH * NWIN * WIN, 256>>>(Sw, Swb, WIN);
    run_gemm(Swb, tVfb, nullptr, gates, nullptr, wPVb, WIN, 1024, 512, 512, 8192, 0, 2048,
             1.f, 0, BATCH * NWIN, NWIN,
             (long)NWIN*WIN*512, (long)WIN*512,
             1024L*8192, 256,
             0,0, (long)SEQ*2048, (long)WIN*2048,
             (long)SEQ*3, (long)WIN*3, 2);

    // output projection
    run_gemm(wPVb, tWo2, bo, nullptr, O, nullptr, (int)N_TOK, 1024, 2048, 2048, 2048, 1024, 0,
             1.f, 0, 1, 1, 0,0,0,0, 0,0, 0,0, 0,0, 0);
    run_gemm(cPVb, tWo0, nullptr, nullptr, O, nullptr, 1024, 1024, 2048, 2048, 2048, 1024, 0,
             1.f, 1, BATCH, 1, 1024L*2048, 0, 0, 0, (long)SEQ*1024, 0, 0,0, 0,0, 0);
    run_gemm(sPVb, tWo1, nullptr, nullptr, O, nullptr, 512, 1024, 2048, 2048, 2048, 1024, 0,
             1.f, 1, BATCH, 1, 512L*2048, 0, 0, 0, (long)SEQ*1024, 0, 0,0, 0,0, 0);

    // residual + layernorm
    final_ln_k<<<(int)N_TOK, 256>>>(O, x, outp);
}

// round 12
// speedup vs baseline: 2.4400x; 1.6205x over previous
#include <cuda_runtime.h>
#include <cuda_fp16.h>
#include <math.h>
#include <stdint.h>

// ---------------- problem constants ----------------
#define BATCH 4
#define SEQ   4096
#define HID_  1024
#define LC    1024
#define KSEL  512
#define WIN   256
#define NWIN  16

static const long N_TOK = (long)BATCH * SEQ;

// ---------------- scratch layout (bytes) ----------------
// All fp16 matrices are plain row-major.
constexpr long O_XB    = 0;                       // x fp16 (16384,1024)
constexpr long O_QFB   = O_XB    + 33554432L;
constexpr long O_KFB   = O_QFB   + 33554432L;
constexpr long O_VF    = O_KFB   + 33554432L;     // Vf fp32 (16384,1024)
constexpr long O_TVFB  = O_VF    + 67108864L;     // Vf^T fp16 4x(1024,4096)
constexpr long O_COMPB = O_TVFB  + 33554432L;     // comp fp16 (4096,1024)
constexpr long O_QCB   = O_COMPB + 8388608L;
constexpr long O_KCB   = O_QCB   + 8388608L;
constexpr long O_VC    = O_KCB   + 8388608L;      // Vc fp32 (4096,1024)
constexpr long O_TVCB  = O_VC    + 16777216L;     // Vc^T fp16 4x(1024,1024)
constexpr long O_SC    = O_TVCB  + 8388608L;      // comp scores fp32 4x(1024,1024)
constexpr long O_SCB   = O_SC    + 16777216L;     // comp P fp16
constexpr long O_CPVB  = O_SCB   + 8388608L;      // comp PV fp16 (4096,1024)
constexpr long O_SQB   = O_CPVB  + 8388608L;      // sel Q fp16 (2048,1024)
constexpr long O_SKB   = O_SQB   + 4194304L;
constexpr long O_SV    = O_SKB   + 4194304L;      // sel V fp32 (2048,1024)
constexpr long O_TSVB  = O_SV    + 8388608L;      // sel V^T fp16 4x(1024,512)
constexpr long O_SS    = O_TSVB  + 4194304L;      // sel scores fp32 4x(512,512)
constexpr long O_SSB   = O_SS    + 4194304L;      // sel P fp16
constexpr long O_SPVB  = O_SSB   + 2097152L;      // sel PV fp16 (2048,1024)
constexpr long O_SW    = O_SPVB  + 4194304L;      // win scores fp32 64x(256,256)
constexpr long O_SWB   = O_SW    + 16777216L;     // win P fp16
constexpr long O_WPVB  = O_SWB   + 8388608L;      // win PV fp16 (16384,1024)
constexpr long O_O     = O_WPVB  + 33554432L;     // O fp32 (16384,1024)
constexpr long O_TWQ   = O_O     + 67108864L;     // Wq^T fp16 (1024,1024)
constexpr long O_TWK   = O_TWQ   + 2097152L;
constexpr long O_TWV   = O_TWK   + 2097152L;
constexpr long O_TWC   = O_TWV   + 2097152L;      // Wc^T fp16 (1024,4096)
constexpr long O_TWO0  = O_TWC   + 8388608L;
constexpr long O_TWO1  = O_TWO0  + 2097152L;
constexpr long O_TWO2  = O_TWO1  + 2097152L;
constexpr long O_GATES = O_TWO2  + 2097152L;
constexpr long O_SCOR  = O_GATES + 196608L;
constexpr long TOTALB  = O_SCOR  + 65536L;

__device__ __align__(1024) unsigned char g_scratch[TOTALB];
__device__ int g_idx[BATCH * KSEL];

typedef __half h16;

// ================= PTX helpers =================
__device__ __forceinline__ uint32_t smem_u32(const void* p) {
    uint32_t a;
    asm("{ .reg .u64 t; cvta.to.shared.u64 t, %1; cvt.u32.u64 %0, t; }" : "=r"(a) : "l"(p));
    return a;
}
__device__ __forceinline__ void cp16(uint32_t dst, const void* src) {
    asm volatile("cp.async.cg.shared.global [%0], [%1], 16;" :: "r"(dst), "l"(src));
}
#define CP_COMMIT() asm volatile("cp.async.commit_group;" ::: "memory")
#define CP_WAIT1()  asm volatile("cp.async.wait_group 1;" ::: "memory")

__device__ __forceinline__ void ldm4(uint32_t* r, uint32_t addr) {
    asm volatile("ldmatrix.sync.aligned.m8n8.x4.shared.b16 {%0,%1,%2,%3}, [%4];"
        : "=r"(r[0]), "=r"(r[1]), "=r"(r[2]), "=r"(r[3]) : "r"(addr));
}
__device__ __forceinline__ void mma16816(float* d, const uint32_t* a, const uint32_t* b) {
    asm volatile(
        "mma.sync.aligned.m16n8k16.row.col.f32.f16.f16.f32 "
        "{%0,%1,%2,%3}, {%4,%5,%6,%7}, {%8,%9}, {%0,%1,%2,%3};"
        : "+f"(d[0]), "+f"(d[1]), "+f"(d[2]), "+f"(d[3])
        : "r"(a[0]), "r"(a[1]), "r"(a[2]), "r"(a[3]), "r"(b[0]), "r"(b[1]));
}

// ================= pipelined HMMA GEMM (pure fp16) =================
// C[M,N] = alpha * A·B^T (+bias)(accum into Cf)(*gate(row)); A (M,K), B (N,K) fp16.
// Tile 128x128, chunk 64 k. 3-stage ring (32KB stages = A 16KB + B 16KB),
// two barriers per chunk (R11-proven skeleton; only MMA count/precision changed).
#define STAGE_B 32768
struct GP {
    const h16 *A, *B;
    const float *bias, *gate;
    float *Cf; h16 *Cb;
    int K, lda, ldb, ldcf, ldcb;
    float alpha;
    int accumulate, zdiv, gcomp;
    long aso, asi, bso, bsi, cfso, cfsi, cbso, cbsi, gso, gsi;
};

__device__ __forceinline__ void stage_load(uint32_t smb, int s, const h16* A, const h16* B,
                                           int lda, int ldb, int k0, int tid) {
    uint32_t sa = smb + s * STAGE_B;
    uint32_t sb2 = sa + 16384;
#pragma unroll
    for (int i = 0; i < 4; i++) {            // A: 128 rows x 8 segs of 16B (128B rows)
        int idx = tid + i * 256;
        int row = idx >> 3, seg = idx & 7;
        cp16(sa + row * 128 + ((seg ^ (row & 7)) << 4), A + (long)row * lda + k0 + seg * 8);
    }
#pragma unroll
    for (int i = 0; i < 4; i++) {            // B: 128 rows x 8 segs of 16B
        int idx = tid + i * 256;
        int row = idx >> 3, seg = idx & 7;
        cp16(sb2 + row * 128 + ((seg ^ (row & 7)) << 4), B + (long)row * ldb + k0 + seg * 8);
    }
    CP_COMMIT();
}

__device__ __forceinline__ uint32_t swzA(uint32_t base, int r, int cb) {
    return base + r * 128 + ((((cb >> 4) ^ (r & 7))) << 4);
}

__global__ void __launch_bounds__(256, 2) gemm_k(GP p) {
    extern __shared__ __align__(1024) char sm[];
    uint32_t smb = smem_u32(sm);
    const int tid = threadIdx.x, lane = tid & 31, wid = tid >> 5;
    const int wm = wid & 3, wn = wid >> 2;

    const long zo = blockIdx.z / p.zdiv, zi = blockIdx.z - zo * (long)p.zdiv;
    const h16* A = p.A + zo * p.aso + zi * p.asi + (long)blockIdx.y * 128 * p.lda;
    const h16* B = p.B + zo * p.bso + zi * p.bsi + (long)blockIdx.x * 128 * p.ldb;

    float acc[2][8][4];
#pragma unroll
    for (int mt = 0; mt < 2; mt++)
#pragma unroll
        for (int nt = 0; nt < 8; nt++)
#pragma unroll
            for (int r = 0; r < 4; r++) acc[mt][nt][r] = 0.f;

    const int nch = p.K >> 6;
    stage_load(smb, 0, A, B, p.lda, p.ldb, 0, tid);
    stage_load(smb, 1, A, B, p.lda, p.ldb, 64, tid);

    for (int c = 0; c < nch; c++) {
        CP_WAIT1();
        __syncthreads();
        if (c + 2 < nch) stage_load(smb, (c + 2) % 3, A, B, p.lda, p.ldb, (c + 2) * 64, tid);
        else CP_COMMIT();

        uint32_t sa = smb + (c % 3) * STAGE_B, sbB = sa + 16384;
#pragma unroll
        for (int ks = 0; ks < 4; ks++) {     // 4 x 16k steps = 64 k per chunk
            uint32_t aH[2][4];
            int ar = wm * 32 + (lane & 15);
            int acb = ks * 32 + ((lane >> 4) << 4);
#pragma unroll
            for (int mt = 0; mt < 2; mt++)
                ldm4(aH[mt], swzA(sa, ar + mt * 16, acb));
            int bcb = ks * 32 + (((lane >> 3) & 1) << 4);
#pragma unroll
            for (int nb = 0; nb < 4; nb++) {
                int brow = wn * 64 + nb * 16 + (lane & 7) + ((lane >> 4) << 3);
                uint32_t h4[4];
                ldm4(h4, swzA(sbB, brow, bcb));
#pragma unroll
                for (int sub = 0; sub < 2; sub++) {
                    int nt = nb * 2 + sub;
#pragma unroll
                    for (int mt = 0; mt < 2; mt++)
                        mma16816(acc[mt][nt], aH[mt], h4 + sub * 2);
                }
            }
        }
        __syncthreads();
    }

    // ---- epilogue ----
    const float* gb = p.gate ? (p.gate + zo * p.gso + zi * p.gsi) : nullptr;
    float* Cf = p.Cf ? (p.Cf + zo * p.cfso + zi * p.cfsi) : nullptr;
    h16* Cb = p.Cb ? (p.Cb + zo * p.cbso + zi * p.cbsi) : nullptr;
    const long rowBase = (long)blockIdx.y * 128 + wm * 32;
    const long colBase = (long)blockIdx.x * 128 + wn * 64;
    const int g = lane >> 2, t = lane & 3;
#pragma unroll
    for (int mt = 0; mt < 2; mt++) {
        long r0 = rowBase + mt * 16 + g, r1 = r0 + 8;
        float gv0 = gb ? gb[r0 * 3 + p.gcomp] : 1.f;
        float gv1 = gb ? gb[r1 * 3 + p.gcomp] : 1.f;
#pragma unroll
        for (int nt = 0; nt < 8; nt++) {
            long c = colBase + nt * 8 + t * 2;
            float b0 = p.bias ? p.bias[c] : 0.f;
            float b1 = p.bias ? p.bias[c + 1] : 0.f;
            float* d = acc[mt][nt];
            float v0 = p.alpha * d[0] + b0, v1 = p.alpha * d[1] + b1;
            float v2 = p.alpha * d[2] + b0, v3 = p.alpha * d[3] + b1;
            if (Cf) {
                long o0 = r0 * (long)p.ldcf + c, o1 = r1 * (long)p.ldcf + c;
                if (p.accumulate) { v0 += Cf[o0]; v1 += Cf[o0 + 1]; v2 += Cf[o1]; v3 += Cf[o1 + 1]; }
                v0 *= gv0; v1 *= gv0; v2 *= gv1; v3 *= gv1;
                *(float2*)(Cf + o0) = make_float2(v0, v1);
                *(float2*)(Cf + o1) = make_float2(v2, v3);
            } else {
                v0 *= gv0; v1 *= gv0; v2 *= gv1; v3 *= gv1;
            }
            if (Cb) {
                __half2 p0, p1;
                p0.x = __float2half_rn(v0); p0.y = __float2half_rn(v1);
                p1.x = __float2half_rn(v2); p1.y = __float2half_rn(v3);
                *(__half2*)(Cb + r0 * (long)p.ldcb + c) = p0;
                *(__half2*)(Cb + r1 * (long)p.ldcb + c) = p1;
            }
        }
    }
}

static void run_gemm(const h16* A, const h16* B, const float* bias, const float* gate,
                     float* Cf, h16* Cb, int M, int N, int K,
                     int lda, int ldb, int ldcf, int ldcb, float alpha,
                     int accum, int nz, int zdiv,
                     long aso, long asi, long bso, long bsi,
                     long cfso, long cfsi, long cbso, long cbsi,
                     long gso, long gsi, int gcomp) {
    GP p;
    p.A = A; p.B = B; p.bias = bias; p.gate = gate; p.Cf = Cf; p.Cb = Cb;
    p.K = K; p.lda = lda; p.ldb = ldb; p.ldcf = ldcf; p.ldcb = ldcb;
    p.alpha = alpha; p.accumulate = accum; p.zdiv = zdiv; p.gcomp = gcomp;
    p.aso = aso; p.asi = asi; p.bso = bso; p.bsi = bsi;
    p.cfso = cfso; p.cfsi = cfsi; p.cbso = cbso; p.cbsi = cbsi;
    p.gso = gso; p.gsi = gsi;
    dim3 grid(N / 128, M / 128, nz);
    gemm_k<<<grid, 256, 3 * STAGE_B>>>(p);
}

// ================= straight convert: fp32 -> fp16 (same layout) =================
__global__ void conv_k(const float* __restrict__ in, h16* __restrict__ out, long n4) {
    long i = (long)blockIdx.x * 256 + threadIdx.x;
    if (i >= n4) return;
    long e = i * 4;
    float4 v = *(const float4*)(in + e);
    __half2 a, b;
    a.x = __float2half_rn(v.x); a.y = __float2half_rn(v.y);
    b.x = __float2half_rn(v.z); b.y = __float2half_rn(v.w);
    *(__half2*)(out + e) = a;
    *(__half2*)(out + e + 2) = b;
}

// ================= transpose convert: fp32 (R,C) -> fp16 (C,R), batched =================
__global__ void trconv_k(const float* __restrict__ in, h16* __restrict__ out,
                         int R, int C, long ibs, long obs) {
    __shared__ float tbuf[32][33];
    in += (long)blockIdx.z * ibs;
    out += (long)blockIdx.z * obs;
    int r0 = blockIdx.y * 32, c0 = blockIdx.x * 32;
    int tx = threadIdx.x, ty = threadIdx.y;
#pragma unroll
    for (int i = 0; i < 4; i++)
        tbuf[ty + i * 8][tx] = in[(long)(r0 + ty + i * 8) * C + c0 + tx];
    __syncthreads();
#pragma unroll
    for (int i = 0; i < 4; i++) {
        int oc = ty + i * 8;
        out[(long)(c0 + oc) * R + r0 + tx] = __float2half_rn(tbuf[tx][oc]);
    }
}

// ================= gates + scores =================
__global__ void gates_scores_k(const float* __restrict__ x,
                               const float* __restrict__ Wg, const float* __restrict__ bg,
                               const float* __restrict__ Ws, const float* __restrict__ bs,
                               float* __restrict__ gates, float* __restrict__ scores) {
    int warp = threadIdx.x >> 5, lane = threadIdx.x & 31;
    long t = (long)blockIdx.x * 4 + warp;
    if (t >= N_TOK) return;
    const float* xr = x + t * HID_;
    float a0 = 0.f, a1 = 0.f, a2 = 0.f, a3 = 0.f;
    for (int d = lane; d < HID_; d += 32) {
        float xv = xr[d];
        a0 += xv * Wg[d * 3 + 0];
        a1 += xv * Wg[d * 3 + 1];
        a2 += xv * Wg[d * 3 + 2];
        a3 += xv * Ws[d];
    }
#pragma unroll
    for (int o = 16; o > 0; o >>= 1) {
        a0 += __shfl_down_sync(0xffffffffu, a0, o);
        a1 += __shfl_down_sync(0xffffffffu, a1, o);
        a2 += __shfl_down_sync(0xffffffffu, a2, o);
        a3 += __shfl_down_sync(0xffffffffu, a3, o);
    }
    if (lane == 0) {
        float g0 = 1.f / (1.f + expf(-(a0 + bg[0])));
        float g1 = 1.f / (1.f + expf(-(a1 + bg[1])));
        float g2 = 1.f / (1.f + expf(-(a2 + bg[2])));
        float s = g0 + g1 + g2 + 1e-6f;
        gates[t * 3 + 0] = g0 / s;
        gates[t * 3 + 1] = g1 / s;
        gates[t * 3 + 2] = g2 / s;
        scores[t] = a3 + bs[0];
    }
}

// ================= exact top-k =================
__device__ __forceinline__ bool before_f(float sa, int ia, float sb, int ib) {
    return (sa > sb) || (sa == sb && ia < ib);
}
__global__ void __launch_bounds__(512) topk_k(const float* __restrict__ scores, int* __restrict__ idx_out) {
    __shared__ float s[SEQ];
    __shared__ int id[SEQ];
    __shared__ int sel[KSEL];
    int b = blockIdx.x, tid = threadIdx.x;
    for (int i = tid; i < SEQ; i += 512) { s[i] = scores[(long)b * SEQ + i]; id[i] = i; }
    __syncthreads();
    for (int k = 2; k <= SEQ; k <<= 1)
        for (int j = k >> 1; j > 0; j >>= 1) {
            for (int i = tid; i < SEQ; i += 512) {
                int ixj = i ^ j;
                if (ixj > i) {
                    bool up = ((i & k) == 0);
                    bool ib = before_f(s[i], id[i], s[ixj], id[ixj]);
                    if (up ? !ib : ib) {
                        float ts = s[i]; s[i] = s[ixj]; s[ixj] = ts;
                        int ti = id[i]; id[i] = id[ixj]; id[ixj] = ti;
                    }
                }
            }
            __syncthreads();
        }
    if (tid < KSEL) sel[tid] = id[tid];
    __syncthreads();
    for (int k = 2; k <= KSEL; k <<= 1)
        for (int j = k >> 1; j > 0; j >>= 1) {
            int i = tid;
            if (i < KSEL) {
                int ixj = i ^ j;
                if (ixj > i) {
                    bool up = ((i & k) == 0);
                    if (up ? (sel[i] > sel[ixj]) : (sel[i] < sel[ixj])) {
                        int tt = sel[i]; sel[i] = sel[ixj]; sel[ixj] = tt;
                    }
                }
            }
            __syncthreads();
        }
    if (tid < KSEL) idx_out[b * KSEL + tid] = sel[tid];
}

// ================= gather (fp16 Q/K rows, fp32 V rows) =================
__global__ void gather_k(const h16* __restrict__ Qb, const h16* __restrict__ Kb,
                         const float* __restrict__ V, const int* __restrict__ idx,
                         h16* __restrict__ sq, h16* __restrict__ sk, float* __restrict__ sv) {
    int r = blockIdx.x;
    int b = r >> 9;
    long srow = (long)b * SEQ + idx[r];
    int tid = threadIdx.x;
    const uint4* v4 = (const uint4*)(V + srow * 1024);
    uint4* ov = (uint4*)(sv + (long)r * 1024);
    ov[tid] = v4[tid];                                   // 256 x 16B = 4KB
    if (tid < 128) {
        const uint4* q4 = (const uint4*)(Qb + srow * 1024);
        const uint4* k4 = (const uint4*)(Kb + srow * 1024);
        uint4* oq = (uint4*)(sq + (long)r * 1024);
        uint4* ok = (uint4*)(sk + (long)r * 1024);
        oq[tid] = q4[tid];                               // 128 x 16B = 2KB
        ok[tid] = k4[tid];
    }
}

// ================= softmax (fp32 in, fp16 out) =================
__global__ void softmax_k(const float* __restrict__ S, h16* __restrict__ Pb, int N) {
    __shared__ float buf[1024];
    __shared__ float red[256];
    long base = (long)blockIdx.x * N;
    int tid = threadIdx.x;
    float m = -1e30f;
    for (int i = tid; i < N; i += 256) { float xv = S[base + i]; buf[i] = xv; m = fmaxf(m, xv); }
    red[tid] = m; __syncthreads();
    for (int o = 128; o > 0; o >>= 1) { if (tid < o) red[tid] = fmaxf(red[tid], red[tid + o]); __syncthreads(); }
    m = red[0]; __syncthreads();
    float sum = 0.f;
    for (int i = tid; i < N; i += 256) { float e = expf(buf[i] - m); buf[i] = e; sum += e; }
    red[tid] = sum; __syncthreads();
    for (int o = 128; o > 0; o >>= 1) { if (tid < o) red[tid] += red[tid + o]; __syncthreads(); }
    float inv = 1.f / red[0];
    __syncthreads();
    for (int i = tid; i < N; i += 256)
        Pb[base + i] = __float2half_rn(buf[i] * inv);
}

// ================= residual + layernorm =================
__global__ void final_ln_k(const float* __restrict__ O, const float* __restrict__ x,
                           float* __restrict__ out) {
    long base = (long)blockIdx.x * HID_;
    int tid = threadIdx.x;
    float y[4];
    float s = 0.f, ss = 0.f;
#pragma unroll
    for (int i = 0; i < 4; i++) {
        int c = tid + i * 256;
        float v = 0.5f * (O[base + c] + x[base + c]);
        y[i] = v; s += v; ss += v * v;
    }
    __shared__ float rs[32], rss[32];
    int lane = tid & 31, warp = tid >> 5;
#pragma unroll
    for (int o = 16; o > 0; o >>= 1) {
        s += __shfl_down_sync(0xffffffffu, s, o);
        ss += __shfl_down_sync(0xffffffffu, ss, o);
    }
    if (lane == 0) { rs[warp] = s; rss[warp] = ss; }
    __syncthreads();
    if (warp == 0) {
        s = (lane < 8) ? rs[lane] : 0.f;
        ss = (lane < 8) ? rss[lane] : 0.f;
#pragma unroll
        for (int o = 4; o > 0; o >>= 1) {
            s += __shfl_down_sync(0xffffffffu, s, o);
            ss += __shfl_down_sync(0xffffffffu, ss, o);
        }
        if (lane == 0) { rs[0] = s; rss[0] = ss; }
    }
    __syncthreads();
    float mu = rs[0] * (1.f / HID_);
    float var = rss[0] * (1.f / HID_) - mu * mu;
    float inv = rsqrtf(var + 1e-6f);
#pragma unroll
    for (int i = 0; i < 4; i++) {
        int c = tid + i * 256;
        out[base + c] = (y[i] - mu) * inv;
    }
}

// ================= launch =================
extern "C" void kernel_launch(void* const* d_in, const int* in_sizes, int n_in,
                              void* d_out, int out_size) {
    const float* x  = (const float*)d_in[0];
    const float* Wq = (const float*)d_in[1];
    const float* bq = (const float*)d_in[2];
    const float* Wk = (const float*)d_in[3];
    const float* bk = (const float*)d_in[4];
    const float* Wv = (const float*)d_in[5];
    const float* bv = (const float*)d_in[6];
    const float* Wo = (const float*)d_in[7];
    const float* bo = (const float*)d_in[8];
    const float* Wg = (const float*)d_in[9];
    const float* bg = (const float*)d_in[10];
    const float* Wc = (const float*)d_in[11];
    const float* bc = (const float*)d_in[12];
    const float* Ws = (const float*)d_in[13];
    const float* bs = (const float*)d_in[14];

    cudaFuncSetAttribute(gemm_k, cudaFuncAttributeMaxDynamicSharedMemorySize, 3 * STAGE_B);

    unsigned char* G; cudaGetSymbolAddress((void**)&G, g_scratch);
    int* idxp; cudaGetSymbolAddress((void**)&idxp, g_idx);

    h16* xb    = (h16*)(G + O_XB);
    h16* Qfb   = (h16*)(G + O_QFB);
    h16* Kfb   = (h16*)(G + O_KFB);
    float* Vf  = (float*)(G + O_VF);
    h16* tVfb  = (h16*)(G + O_TVFB);
    h16* compb = (h16*)(G + O_COMPB);
    h16* Qcb   = (h16*)(G + O_QCB);
    h16* Kcb   = (h16*)(G + O_KCB);
    float* Vc  = (float*)(G + O_VC);
    h16* tVcb  = (h16*)(G + O_TVCB);
    float* Sc  = (float*)(G + O_SC);
    h16* Scb   = (h16*)(G + O_SCB);
    h16* cPVb  = (h16*)(G + O_CPVB);
    h16* sQb   = (h16*)(G + O_SQB);
    h16* sKb   = (h16*)(G + O_SKB);
    float* sV  = (float*)(G + O_SV);
    h16* tSvb  = (h16*)(G + O_TSVB);
    float* Ss  = (float*)(G + O_SS);
    h16* Ssb   = (h16*)(G + O_SSB);
    h16* sPVb  = (h16*)(G + O_SPVB);
    float* Sw  = (float*)(G + O_SW);
    h16* Swb   = (h16*)(G + O_SWB);
    h16* wPVb  = (h16*)(G + O_WPVB);
    float* O   = (float*)(G + O_O);
    h16* tWq   = (h16*)(G + O_TWQ);
    h16* tWk   = (h16*)(G + O_TWK);
    h16* tWv   = (h16*)(G + O_TWV);
    h16* tWc   = (h16*)(G + O_TWC);
    h16* tWo0  = (h16*)(G + O_TWO0);
    h16* tWo1  = (h16*)(G + O_TWO1);
    h16* tWo2  = (h16*)(G + O_TWO2);
    float* gates  = (float*)(G + O_GATES);
    float* scores = (float*)(G + O_SCOR);
    float* outp = (float*)d_out;

    const float SCALE = 0.125f;
    dim3 trb(32, 8);

    // conversions, then big comp GEMM
    conv_k<<<(int)((N_TOK * HID_ / 4 + 255) / 256), 256>>>(x, xb, N_TOK * HID_ / 4);
    trconv_k<<<dim3(32, 32, 1), trb>>>(Wq, tWq, 1024, 1024, 0, 0);
    trconv_k<<<dim3(32, 32, 1), trb>>>(Wk, tWk, 1024, 1024, 0, 0);
    trconv_k<<<dim3(32, 32, 1), trb>>>(Wv, tWv, 1024, 1024, 0, 0);
    trconv_k<<<dim3(32, 128, 1), trb>>>(Wc, tWc, 4096, 1024, 0, 0);
    run_gemm(xb, tWc, bc, nullptr, nullptr, compb, 4096, 1024, 4096, 4096, 4096, 0, 1024,
             1.f, 0, 1, 1, 0,0,0,0, 0,0, 0,0, 0,0, 0);

    trconv_k<<<dim3(32, 32, 1), trb>>>(Wo, tWo0, 1024, 1024, 0, 0);
    trconv_k<<<dim3(32, 32, 1), trb>>>(Wo + 1024L * 1024, tWo1, 1024, 1024, 0, 0);
    trconv_k<<<dim3(32, 32, 1), trb>>>(Wo + 2048L * 1024, tWo2, 1024, 1024, 0, 0);

    gates_scores_k<<<(int)(N_TOK / 4), 128>>>(x, Wg, bg, Ws, bs, gates, scores);
    topk_k<<<BATCH, 512>>>(scores, idxp);

    // full Q/K/V projections
    run_gemm(xb, tWq, bq, nullptr, nullptr, Qfb, (int)N_TOK, 1024, 1024, 1024, 1024, 0, 1024,
             1.f, 0, 1, 1, 0,0,0,0, 0,0, 0,0, 0,0, 0);
    run_gemm(xb, tWk, bk, nullptr, nullptr, Kfb, (int)N_TOK, 1024, 1024, 1024, 1024, 0, 1024,
             1.f, 0, 1, 1, 0,0,0,0, 0,0, 0,0, 0,0, 0);
    run_gemm(xb, tWv, bv, nullptr, Vf, nullptr, (int)N_TOK, 1024, 1024, 1024, 1024, 1024, 0,
             1.f, 0, 1, 1, 0,0,0,0, 0,0, 0,0, 0,0, 0);

    // compressed Q/K/V
    run_gemm(compb, tWq, bq, nullptr, nullptr, Qcb, 4096, 1024, 1024, 1024, 1024, 0, 1024,
             1.f, 0, 1, 1, 0,0,0,0, 0,0, 0,0, 0,0, 0);
    run_gemm(compb, tWk, bk, nullptr, nullptr, Kcb, 4096, 1024, 1024, 1024, 1024, 0, 1024,
             1.f, 0, 1, 1, 0,0,0,0, 0,0, 0,0, 0,0, 0);
    run_gemm(compb, tWv, bv, nullptr, Vc, nullptr, 4096, 1024, 1024, 1024, 1024, 1024, 0,
             1.f, 0, 1, 1, 0,0,0,0, 0,0, 0,0, 0,0, 0);

    // compressed attention
    run_gemm(Qcb, Kcb, nullptr, nullptr, Sc, nullptr, 1024, 1024, 1024, 1024, 1024, 1024, 0,
             SCALE, 0, BATCH, 1, 1024L*1024, 0, 1024L*1024, 0, 1024L*1024, 0, 0,0, 0,0, 0);
    softmax_k<<<BATCH * 1024, 256>>>(Sc, Scb, 1024);
    trconv_k<<<dim3(32, 32, BATCH), trb>>>(Vc, tVcb, 1024, 1024, 1024L*1024, 1024L*1024);
    run_gemm(Scb, tVcb, nullptr, gates, nullptr, cPVb, 1024, 1024, 1024, 1024, 1024, 0, 1024,
             1.f, 0, BATCH, 1, 1024L*1024, 0, 1024L*1024, 0, 0,0, 1024L*1024, 0,
             (long)SEQ*3, 0, 0);

    // selected branch
    gather_k<<<BATCH * KSEL, 256>>>(Qfb, Kfb, Vf, idxp, sQb, sKb, sV);
    run_gemm(sQb, sKb, nullptr, nullptr, Ss, nullptr, 512, 512, 1024, 1024, 1024, 512, 0,
             SCALE, 0, BATCH, 1, 512L*1024, 0, 512L*1024, 0, 512L*512, 0, 0,0, 0,0, 0);
    softmax_k<<<BATCH * 512, 256>>>(Ss, Ssb, 512);
    trconv_k<<<dim3(32, 16, BATCH), trb>>>(sV, tSvb, 512, 1024, 512L*1024, 1024L*512);
    run_gemm(Ssb, tSvb, nullptr, gates, nullptr, sPVb, 512, 1024, 512, 512, 512, 0, 1024,
             1.f, 0, BATCH, 1, 512L*512, 0, 1024L*512, 0, 0,0, 512L*1024, 0,
             (long)SEQ*3, 0, 1);

    // window branch
    trconv_k<<<dim3(32, 128, BATCH), trb>>>(Vf, tVfb, 4096, 1024, 4096L*1024, 1024L*4096);
    run_gemm(Qfb, Kfb, nullptr, nullptr, Sw, nullptr, WIN, WIN, 1024, 1024, 1024, WIN, 0,
             SCALE, 0, BATCH * NWIN, NWIN,
             (long)SEQ*1024, 128L*1024, (long)SEQ*1024, 128L*1024,
             (long)NWIN*WIN*WIN, (long)WIN*WIN, 0,0, 0,0, 0);
    softmax_k<<<BATCH * NWIN * WIN, 256>>>(Sw, Swb, WIN);
    run_gemm(Swb, tVfb, nullptr, gates, nullptr, wPVb, WIN, 1024, WIN, WIN, 4096, 0, 1024,
             1.f, 0, BATCH * NWIN, NWIN,
             (long)NWIN*WIN*WIN, (long)WIN*WIN,
             1024L*4096, 128,
             0,0, (long)SEQ*1024, (long)WIN*1024,
             (long)SEQ*3, (long)WIN*3, 2);

    // output projection
    run_gemm(wPVb, tWo2, bo, nullptr, O, nullptr, (int)N_TOK, 1024, 1024, 1024, 1024, 1024, 0,
             1.f, 0, 1, 1, 0,0,0,0, 0,0, 0,0, 0,0, 0);
    run_gemm(cPVb, tWo0, nullptr, nullptr, O, nullptr, 1024, 1024, 1024, 1024, 1024, 1024, 0,
             1.f, 1, BATCH, 1, 1024L*1024, 0, 0, 0, (long)SEQ*1024, 0, 0,0, 0,0, 0);
    run_gemm(sPVb, tWo1, nullptr, nullptr, O, nullptr, 512, 1024, 1024, 1024, 1024, 1024, 0,
             1.f, 1, BATCH, 1, 512L*1024, 0, 0, 0, (long)SEQ*1024, 0, 0,0, 0,0, 0);

    // residual + layernorm
    final_ln_k<<<(int)N_TOK, 256>>>(O, x, outp);
}

// round 14
// speedup vs baseline: 2.4890x; 1.0201x over previous
#include <cuda_runtime.h>
#include <cuda_fp16.h>
#include <math.h>
#include <stdint.h>

// ---------------- problem constants ----------------
#define BATCH 4
#define SEQ   4096
#define HID_  1024
#define LC    1024
#define KSEL  512
#define WIN   256
#define NWIN  16

static const long N_TOK = (long)BATCH * SEQ;

// ---------------- scratch layout (bytes) ----------------
constexpr long O_XB    = 0;            // x fp16 (16384,1024)
constexpr long O_QKV   = 33554432L;    // fused QKV fp16 (16384,3072): q|k|v col blocks
constexpr long O_CQKV  = 134217728L;   // fused comp QKV fp16 (4096,3072)
constexpr long O_COMPB = 159383552L;   // comp fp16 (4096,1024)
constexpr long O_TVFB  = 167772160L;   // Vf^T fp16 4x(1024,4096)
constexpr long O_TVCB  = 201326592L;   // Vc^T fp16 4x(1024,1024)
constexpr long O_SC    = 209715200L;   // comp scores fp32 4x(1024,1024)
constexpr long O_SCB   = 226492416L;   // comp P fp16
constexpr long O_CPVB  = 234881024L;   // comp PV fp16 (4096,1024)
constexpr long O_SQB   = 243269632L;   // sel Q fp16 (2048,1024)
constexpr long O_SKB   = 247463936L;
constexpr long O_SVB   = 251658240L;   // sel V fp16 (2048,1024)
constexpr long O_TSVB  = 255852544L;   // sel V^T fp16 4x(1024,512)
constexpr long O_SS    = 260046848L;   // sel scores fp32 4x(512,512)
constexpr long O_SSB   = 264241152L;   // sel P fp16
constexpr long O_SPVB  = 266338304L;   // sel PV fp16 (2048,1024)
constexpr long O_SW    = 270532608L;   // win scores fp32 64x(256,256)
constexpr long O_SWB   = 287309824L;   // win P fp16
constexpr long O_WPVB  = 295698432L;   // win PV fp16 (16384,1024)
constexpr long O_O     = 329252864L;   // O fp32 (16384,1024)
constexpr long O_TW    = 396361728L;   // [Wq|Wk|Wv]^T fp16 (3072,1024)
constexpr long O_TWC   = 402653184L;   // Wc^T fp16 (1024,4096)
constexpr long O_TWO0  = 411041792L;
constexpr long O_TWO1  = 413138944L;
constexpr long O_TWO2  = 415236096L;
constexpr long O_GATES = 417333248L;
constexpr long O_SCOR  = 417529856L;
constexpr long O_BIAS  = 417595392L;   // concat bias fp32 (3072)
constexpr long TOTALB  = 417611776L;

__device__ __align__(1024) unsigned char g_scratch[TOTALB];
__device__ int g_idx[BATCH * KSEL];

typedef __half h16;

// ================= PTX helpers =================
__device__ __forceinline__ uint32_t smem_u32(const void* p) {
    uint32_t a;
    asm("{ .reg .u64 t; cvta.to.shared.u64 t, %1; cvt.u32.u64 %0, t; }" : "=r"(a) : "l"(p));
    return a;
}
__device__ __forceinline__ void cp16(uint32_t dst, const void* src) {
    asm volatile("cp.async.cg.shared.global [%0], [%1], 16;" :: "r"(dst), "l"(src));
}
#define CP_COMMIT() asm volatile("cp.async.commit_group;" ::: "memory")
#define CP_WAIT1()  asm volatile("cp.async.wait_group 1;" ::: "memory")

__device__ __forceinline__ void ldm4(uint32_t* r, uint32_t addr) {
    asm volatile("ldmatrix.sync.aligned.m8n8.x4.shared.b16 {%0,%1,%2,%3}, [%4];"
        : "=r"(r[0]), "=r"(r[1]), "=r"(r[2]), "=r"(r[3]) : "r"(addr));
}
__device__ __forceinline__ void mma16816(float* d, const uint32_t* a, const uint32_t* b) {
    asm volatile(
        "mma.sync.aligned.m16n8k16.row.col.f32.f16.f16.f32 "
        "{%0,%1,%2,%3}, {%4,%5,%6,%7}, {%8,%9}, {%0,%1,%2,%3};"
        : "+f"(d[0]), "+f"(d[1]), "+f"(d[2]), "+f"(d[3])
        : "r"(a[0]), "r"(a[1]), "r"(a[2]), "r"(a[3]), "r"(b[0]), "r"(b[1]));
}

// ================= pipelined HMMA GEMM (pure fp16) — R12-proven, unchanged =================
#define STAGE_B 32768
struct GP {
    const h16 *A, *B;
    const float *bias, *gate;
    float *Cf; h16 *Cb;
    int K, lda, ldb, ldcf, ldcb;
    float alpha;
    int accumulate, zdiv, gcomp;
    long aso, asi, bso, bsi, cfso, cfsi, cbso, cbsi, gso, gsi;
};

__device__ __forceinline__ void stage_load(uint32_t smb, int s, const h16* A, const h16* B,
                                           int lda, int ldb, int k0, int tid) {
    uint32_t sa = smb + s * STAGE_B;
    uint32_t sb2 = sa + 16384;
#pragma unroll
    for (int i = 0; i < 4; i++) {
        int idx = tid + i * 256;
        int row = idx >> 3, seg = idx & 7;
        cp16(sa + row * 128 + ((seg ^ (row & 7)) << 4), A + (long)row * lda + k0 + seg * 8);
    }
#pragma unroll
    for (int i = 0; i < 4; i++) {
        int idx = tid + i * 256;
        int row = idx >> 3, seg = idx & 7;
        cp16(sb2 + row * 128 + ((seg ^ (row & 7)) << 4), B + (long)row * ldb + k0 + seg * 8);
    }
    CP_COMMIT();
}

__device__ __forceinline__ uint32_t swzA(uint32_t base, int r, int cb) {
    return base + r * 128 + ((((cb >> 4) ^ (r & 7))) << 4);
}

__global__ void __launch_bounds__(256, 2) gemm_k(GP p) {
    extern __shared__ __align__(1024) char sm[];
    uint32_t smb = smem_u32(sm);
    const int tid = threadIdx.x, lane = tid & 31, wid = tid >> 5;
    const int wm = wid & 3, wn = wid >> 2;

    const long zo = blockIdx.z / p.zdiv, zi = blockIdx.z - zo * (long)p.zdiv;
    const h16* A = p.A + zo * p.aso + zi * p.asi + (long)blockIdx.y * 128 * p.lda;
    const h16* B = p.B + zo * p.bso + zi * p.bsi + (long)blockIdx.x * 128 * p.ldb;

    float acc[2][8][4];
#pragma unroll
    for (int mt = 0; mt < 2; mt++)
#pragma unroll
        for (int nt = 0; nt < 8; nt++)
#pragma unroll
            for (int r = 0; r < 4; r++) acc[mt][nt][r] = 0.f;

    const int nch = p.K >> 6;
    stage_load(smb, 0, A, B, p.lda, p.ldb, 0, tid);
    stage_load(smb, 1, A, B, p.lda, p.ldb, 64, tid);

    for (int c = 0; c < nch; c++) {
        CP_WAIT1();
        __syncthreads();
        if (c + 2 < nch) stage_load(smb, (c + 2) % 3, A, B, p.lda, p.ldb, (c + 2) * 64, tid);
        else CP_COMMIT();

        uint32_t sa = smb + (c % 3) * STAGE_B, sbB = sa + 16384;
#pragma unroll
        for (int ks = 0; ks < 4; ks++) {
            uint32_t aH[2][4];
            int ar = wm * 32 + (lane & 15);
            int acb = ks * 32 + ((lane >> 4) << 4);
#pragma unroll
            for (int mt = 0; mt < 2; mt++)
                ldm4(aH[mt], swzA(sa, ar + mt * 16, acb));
            int bcb = ks * 32 + (((lane >> 3) & 1) << 4);
#pragma unroll
            for (int nb = 0; nb < 4; nb++) {
                int brow = wn * 64 + nb * 16 + (lane & 7) + ((lane >> 4) << 3);
                uint32_t h4[4];
                ldm4(h4, swzA(sbB, brow, bcb));
#pragma unroll
                for (int sub = 0; sub < 2; sub++) {
                    int nt = nb * 2 + sub;
#pragma unroll
                    for (int mt = 0; mt < 2; mt++)
                        mma16816(acc[mt][nt], aH[mt], h4 + sub * 2);
                }
            }
        }
        __syncthreads();
    }

    // ---- epilogue ----
    const float* gb = p.gate ? (p.gate + zo * p.gso + zi * p.gsi) : nullptr;
    float* Cf = p.Cf ? (p.Cf + zo * p.cfso + zi * p.cfsi) : nullptr;
    h16* Cb = p.Cb ? (p.Cb + zo * p.cbso + zi * p.cbsi) : nullptr;
    const long rowBase = (long)blockIdx.y * 128 + wm * 32;
    const long colBase = (long)blockIdx.x * 128 + wn * 64;
    const int g = lane >> 2, t = lane & 3;
#pragma unroll
    for (int mt = 0; mt < 2; mt++) {
        long r0 = rowBase + mt * 16 + g, r1 = r0 + 8;
        float gv0 = gb ? gb[r0 * 3 + p.gcomp] : 1.f;
        float gv1 = gb ? gb[r1 * 3 + p.gcomp] : 1.f;
#pragma unroll
        for (int nt = 0; nt < 8; nt++) {
            long c = colBase + nt * 8 + t * 2;
            float b0 = p.bias ? p.bias[c] : 0.f;
            float b1 = p.bias ? p.bias[c + 1] : 0.f;
            float* d = acc[mt][nt];
            float v0 = p.alpha * d[0] + b0, v1 = p.alpha * d[1] + b1;
            float v2 = p.alpha * d[2] + b0, v3 = p.alpha * d[3] + b1;
            if (Cf) {
                long o0 = r0 * (long)p.ldcf + c, o1 = r1 * (long)p.ldcf + c;
                if (p.accumulate) { v0 += Cf[o0]; v1 += Cf[o0 + 1]; v2 += Cf[o1]; v3 += Cf[o1 + 1]; }
                v0 *= gv0; v1 *= gv0; v2 *= gv1; v3 *= gv1;
                *(float2*)(Cf + o0) = make_float2(v0, v1);
                *(float2*)(Cf + o1) = make_float2(v2, v3);
            } else {
                v0 *= gv0; v1 *= gv0; v2 *= gv1; v3 *= gv1;
            }
            if (Cb) {
                __half2 p0, p1;
                p0.x = __float2half_rn(v0); p0.y = __float2half_rn(v1);
                p1.x = __float2half_rn(v2); p1.y = __float2half_rn(v3);
                *(__half2*)(Cb + r0 * (long)p.ldcb + c) = p0;
                *(__half2*)(Cb + r1 * (long)p.ldcb + c) = p1;
            }
        }
    }
}

static void run_gemm(const h16* A, const h16* B, const float* bias, const float* gate,
                     float* Cf, h16* Cb, int M, int N, int K,
                     int lda, int ldb, int ldcf, int ldcb, float alpha,
                     int accum, int nz, int zdiv,
                     long aso, long asi, long bso, long bsi,
                     long cfso, long cfsi, long cbso, long cbsi,
                     long gso, long gsi, int gcomp) {
    GP p;
    p.A = A; p.B = B; p.bias = bias; p.gate = gate; p.Cf = Cf; p.Cb = Cb;
    p.K = K; p.lda = lda; p.ldb = ldb; p.ldcf = ldcf; p.ldcb = ldcb;
    p.alpha = alpha; p.accumulate = accum; p.zdiv = zdiv; p.gcomp = gcomp;
    p.aso = aso; p.asi = asi; p.bso = bso; p.bsi = bsi;
    p.cfso = cfso; p.cfsi = cfsi; p.cbso = cbso; p.cbsi = cbsi;
    p.gso = gso; p.gsi = gsi;
    dim3 grid(N / 128, M / 128, nz);
    gemm_k<<<grid, 256, 3 * STAGE_B>>>(p);
}

// ================= straight convert: fp32 -> fp16 =================
__global__ void conv_k(const float* __restrict__ in, h16* __restrict__ out, long n4) {
    long i = (long)blockIdx.x * 256 + threadIdx.x;
    if (i >= n4) return;
    long e = i * 4;
    float4 v = *(const float4*)(in + e);
    __half2 a, b;
    a.x = __float2half_rn(v.x); a.y = __float2half_rn(v.y);
    b.x = __float2half_rn(v.z); b.y = __float2half_rn(v.w);
    *(__half2*)(out + e) = a;
    *(__half2*)(out + e + 2) = b;
}

// ================= bias concat =================
__global__ void biascat_k(const float* __restrict__ bq, const float* __restrict__ bk,
                          const float* __restrict__ bv, float* __restrict__ out) {
    int i = blockIdx.x * 256 + threadIdx.x;
    if (i < 1024) out[i] = bq[i];
    else if (i < 2048) out[i] = bk[i - 1024];
    else if (i < 3072) out[i] = bv[i - 2048];
}

// ================= transpose convert: fp32 (R,C) -> fp16 (C,R) =================
__global__ void trconv_k(const float* __restrict__ in, h16* __restrict__ out,
                         int R, int C, long ibs, long obs) {
    __shared__ float tbuf[32][33];
    in += (long)blockIdx.z * ibs;
    out += (long)blockIdx.z * obs;
    int r0 = blockIdx.y * 32, c0 = blockIdx.x * 32;
    int tx = threadIdx.x, ty = threadIdx.y;
#pragma unroll
    for (int i = 0; i < 4; i++)
        tbuf[ty + i * 8][tx] = in[(long)(r0 + ty + i * 8) * C + c0 + tx];
    __syncthreads();
#pragma unroll
    for (int i = 0; i < 4; i++) {
        int oc = ty + i * 8;
        out[(long)(c0 + oc) * R + r0 + tx] = __float2half_rn(tbuf[tx][oc]);
    }
}

// ================= transpose fp16 (R,C logical; row stride ldi) -> fp16 (C,R) =================
__global__ void trconv_h(const h16* __restrict__ in, h16* __restrict__ out,
                         int R, int ldi, long ibs, long obs) {
    __shared__ h16 tbuf[32][33];
    in += (long)blockIdx.z * ibs;
    out += (long)blockIdx.z * obs;
    int r0 = blockIdx.y * 32, c0 = blockIdx.x * 32;
    int tx = threadIdx.x, ty = threadIdx.y;
#pragma unroll
    for (int i = 0; i < 4; i++)
        tbuf[ty + i * 8][tx] = in[(long)(r0 + ty + i * 8) * ldi + c0 + tx];
    __syncthreads();
#pragma unroll
    for (int i = 0; i < 4; i++) {
        int oc = ty + i * 8;
        out[(long)(c0 + oc) * R + r0 + tx] = tbuf[tx][oc];
    }
}

// ================= gates + scores =================
__global__ void gates_scores_k(const float* __restrict__ x,
                               const float* __restrict__ Wg, const float* __restrict__ bg,
                               const float* __restrict__ Ws, const float* __restrict__ bs,
                               float* __restrict__ gates, float* __restrict__ scores) {
    int warp = threadIdx.x >> 5, lane = threadIdx.x & 31;
    long t = (long)blockIdx.x * 4 + warp;
    if (t >= N_TOK) return;
    const float* xr = x + t * HID_;
    float a0 = 0.f, a1 = 0.f, a2 = 0.f, a3 = 0.f;
    for (int d = lane; d < HID_; d += 32) {
        float xv = xr[d];
        a0 += xv * Wg[d * 3 + 0];
        a1 += xv * Wg[d * 3 + 1];
        a2 += xv * Wg[d * 3 + 2];
        a3 += xv * Ws[d];
    }
#pragma unroll
    for (int o = 16; o > 0; o >>= 1) {
        a0 += __shfl_down_sync(0xffffffffu, a0, o);
        a1 += __shfl_down_sync(0xffffffffu, a1, o);
        a2 += __shfl_down_sync(0xffffffffu, a2, o);
        a3 += __shfl_down_sync(0xffffffffu, a3, o);
    }
    if (lane == 0) {
        float g0 = 1.f / (1.f + expf(-(a0 + bg[0])));
        float g1 = 1.f / (1.f + expf(-(a1 + bg[1])));
        float g2 = 1.f / (1.f + expf(-(a2 + bg[2])));
        float s = g0 + g1 + g2 + 1e-6f;
        gates[t * 3 + 0] = g0 / s;
        gates[t * 3 + 1] = g1 / s;
        gates[t * 3 + 2] = g2 / s;
        scores[t] = a3 + bs[0];
    }
}

// ================= exact top-k =================
__device__ __forceinline__ bool before_f(float sa, int ia, float sb, int ib) {
    return (sa > sb) || (sa == sb && ia < ib);
}
__global__ void __launch_bounds__(512) topk_k(const float* __restrict__ scores, int* __restrict__ idx_out) {
    __shared__ float s[SEQ];
    __shared__ int id[SEQ];
    __shared__ int sel[KSEL];
    int b = blockIdx.x, tid = threadIdx.x;
    for (int i = tid; i < SEQ; i += 512) { s[i] = scores[(long)b * SEQ + i]; id[i] = i; }
    __syncthreads();
    for (int k = 2; k <= SEQ; k <<= 1)
        for (int j = k >> 1; j > 0; j >>= 1) {
            for (int i = tid; i < SEQ; i += 512) {
                int ixj = i ^ j;
                if (ixj > i) {
                    bool up = ((i & k) == 0);
                    bool ib = before_f(s[i], id[i], s[ixj], id[ixj]);
                    if (up ? !ib : ib) {
                        float ts = s[i]; s[i] = s[ixj]; s[ixj] = ts;
                        int ti = id[i]; id[i] = id[ixj]; id[ixj] = ti;
                    }
                }
            }
            __syncthreads();
        }
    if (tid < KSEL) sel[tid] = id[tid];
    __syncthreads();
    for (int k = 2; k <= KSEL; k <<= 1)
        for (int j = k >> 1; j > 0; j >>= 1) {
            int i = tid;
            if (i < KSEL) {
                int ixj = i ^ j;
                if (ixj > i) {
                    bool up = ((i & k) == 0);
                    if (up ? (sel[i] > sel[ixj]) : (sel[i] < sel[ixj])) {
                        int tt = sel[i]; sel[i] = sel[ixj]; sel[ixj] = tt;
                    }
                }
            }
            __syncthreads();
        }
    if (tid < KSEL) idx_out[b * KSEL + tid] = sel[tid];
}

// ================= gather from fused QKV (fp16) =================
__global__ void gather_k(const h16* __restrict__ QKV, const int* __restrict__ idx,
                         h16* __restrict__ sq, h16* __restrict__ sk, h16* __restrict__ sv) {
    int r = blockIdx.x;
    int b = r >> 9;
    long srow = (long)b * SEQ + idx[r];
    int tid = threadIdx.x;   // 128 threads
    const uint4* src = (const uint4*)(QKV + srow * 3072);   // 384 uint4
    ((uint4*)(sq + (long)r * 1024))[tid] = src[tid];
    ((uint4*)(sk + (long)r * 1024))[tid] = src[128 + tid];
    ((uint4*)(sv + (long)r * 1024))[tid] = src[256 + tid];
}

// ================= softmax (fp32 in, fp16 out) =================
__global__ void softmax_k(const float* __restrict__ S, h16* __restrict__ Pb, int N) {
    __shared__ float buf[1024];
    __shared__ float red[256];
    long base = (long)blockIdx.x * N;
    int tid = threadIdx.x;
    float m = -1e30f;
    for (int i = tid; i < N; i += 256) { float xv = S[base + i]; buf[i] = xv; m = fmaxf(m, xv); }
    red[tid] = m; __syncthreads();
    for (int o = 128; o > 0; o >>= 1) { if (tid < o) red[tid] = fmaxf(red[tid], red[tid + o]); __syncthreads(); }
    m = red[0]; __syncthreads();
    float sum = 0.f;
    for (int i = tid; i < N; i += 256) { float e = expf(buf[i] - m); buf[i] = e; sum += e; }
    red[tid] = sum; __syncthreads();
    for (int o = 128; o > 0; o >>= 1) { if (tid < o) red[tid] += red[tid + o]; __syncthreads(); }
    float inv = 1.f / red[0];
    __syncthreads();
    for (int i = tid; i < N; i += 256)
        Pb[base + i] = __float2half_rn(buf[i] * inv);
}

// ================= residual + layernorm =================
__global__ void final_ln_k(const float* __restrict__ O, const float* __restrict__ x,
                           float* __restrict__ out) {
    long base = (long)blockIdx.x * HID_;
    int tid = threadIdx.x;
    float y[4];
    float s = 0.f, ss = 0.f;
#pragma unroll
    for (int i = 0; i < 4; i++) {
        int c = tid + i * 256;
        float v = 0.5f * (O[base + c] + x[base + c]);
        y[i] = v; s += v; ss += v * v;
    }
    __shared__ float rs[32], rss[32];
    int lane = tid & 31, warp = tid >> 5;
#pragma unroll
    for (int o = 16; o > 0; o >>= 1) {
        s += __shfl_down_sync(0xffffffffu, s, o);
        ss += __shfl_down_sync(0xffffffffu, ss, o);
    }
    if (lane == 0) { rs[warp] = s; rss[warp] = ss; }
    __syncthreads();
    if (warp == 0) {
        s = (lane < 8) ? rs[lane] : 0.f;
        ss = (lane < 8) ? rss[lane] : 0.f;
#pragma unroll
        for (int o = 4; o > 0; o >>= 1) {
            s += __shfl_down_sync(0xffffffffu, s, o);
            ss += __shfl_down_sync(0xffffffffu, ss, o);
        }
        if (lane == 0) { rs[0] = s; rss[0] = ss; }
    }
    __syncthreads();
    float mu = rs[0] * (1.f / HID_);
    float var = rss[0] * (1.f / HID_) - mu * mu;
    float inv = rsqrtf(var + 1e-6f);
#pragma unroll
    for (int i = 0; i < 4; i++) {
        int c = tid + i * 256;
        out[base + c] = (y[i] - mu) * inv;
    }
}

// ================= launch =================
extern "C" void kernel_launch(void* const* d_in, const int* in_sizes, int n_in,
                              void* d_out, int out_size) {
    const float* x  = (const float*)d_in[0];
    const float* Wq = (const float*)d_in[1];
    const float* bq = (const float*)d_in[2];
    const float* Wk = (const float*)d_in[3];
    const float* bk = (const float*)d_in[4];
    const float* Wv = (const float*)d_in[5];
    const float* bv = (const float*)d_in[6];
    const float* Wo = (const float*)d_in[7];
    const float* bo = (const float*)d_in[8];
    const float* Wg = (const float*)d_in[9];
    const float* bg = (const float*)d_in[10];
    const float* Wc = (const float*)d_in[11];
    const float* bc = (const float*)d_in[12];
    const float* Ws = (const float*)d_in[13];
    const float* bs = (const float*)d_in[14];

    cudaFuncSetAttribute(gemm_k, cudaFuncAttributeMaxDynamicSharedMemorySize, 3 * STAGE_B);

    unsigned char* G; cudaGetSymbolAddress((void**)&G, g_scratch);
    int* idxp; cudaGetSymbolAddress((void**)&idxp, g_idx);

    h16* xb    = (h16*)(G + O_XB);
    h16* QKV   = (h16*)(G + O_QKV);
    h16* cQKV  = (h16*)(G + O_CQKV);
    h16* compb = (h16*)(G + O_COMPB);
    h16* tVfb  = (h16*)(G + O_TVFB);
    h16* tVcb  = (h16*)(G + O_TVCB);
    float* Sc  = (float*)(G + O_SC);
    h16* Scb   = (h16*)(G + O_SCB);
    h16* cPVb  = (h16*)(G + O_CPVB);
    h16* sQb   = (h16*)(G + O_SQB);
    h16* sKb   = (h16*)(G + O_SKB);
    h16* sVb   = (h16*)(G + O_SVB);
    h16* tSvb  = (h16*)(G + O_TSVB);
    float* Ss  = (float*)(G + O_SS);
    h16* Ssb   = (h16*)(G + O_SSB);
    h16* sPVb  = (h16*)(G + O_SPVB);
    float* Sw  = (float*)(G + O_SW);
    h16* Swb   = (h16*)(G + O_SWB);
    h16* wPVb  = (h16*)(G + O_WPVB);
    float* O   = (float*)(G + O_O);
    h16* tW    = (h16*)(G + O_TW);
    h16* tWc   = (h16*)(G + O_TWC);
    h16* tWo0  = (h16*)(G + O_TWO0);
    h16* tWo1  = (h16*)(G + O_TWO1);
    h16* tWo2  = (h16*)(G + O_TWO2);
    float* gates  = (float*)(G + O_GATES);
    float* scores = (float*)(G + O_SCOR);
    float* biasqkv = (float*)(G + O_BIAS);
    float* outp = (float*)d_out;

    const float SCALE = 0.125f;
    dim3 trb(32, 8);

    // conversions / weight prep
    conv_k<<<(int)((N_TOK * HID_ / 4 + 255) / 256), 256>>>(x, xb, N_TOK * HID_ / 4);
    biascat_k<<<12, 256>>>(bq, bk, bv, biasqkv);
    trconv_k<<<dim3(32, 32, 1), trb>>>(Wq, tW, 1024, 1024, 0, 0);
    trconv_k<<<dim3(32, 32, 1), trb>>>(Wk, tW + 1024L * 1024, 1024, 1024, 0, 0);
    trconv_k<<<dim3(32, 32, 1), trb>>>(Wv, tW + 2048L * 1024, 1024, 1024, 0, 0);
    trconv_k<<<dim3(32, 128, 1), trb>>>(Wc, tWc, 4096, 1024, 0, 0);
    trconv_k<<<dim3(32, 32, 1), trb>>>(Wo, tWo0, 1024, 1024, 0, 0);
    trconv_k<<<dim3(32, 32, 1), trb>>>(Wo + 1024L * 1024, tWo1, 1024, 1024, 0, 0);
    trconv_k<<<dim3(32, 32, 1), trb>>>(Wo + 2048L * 1024, tWo2, 1024, 1024, 0, 0);

    gates_scores_k<<<(int)(N_TOK / 4), 128>>>(x, Wg, bg, Ws, bs, gates, scores);
    topk_k<<<BATCH, 512>>>(scores, idxp);

    // fused full QKV projection: (16384,3072)
    run_gemm(xb, tW, biasqkv, nullptr, nullptr, QKV, (int)N_TOK, 3072, 1024,
             1024, 1024, 0, 3072, 1.f, 0, 1, 1, 0,0,0,0, 0,0, 0,0, 0,0, 0);

    // compressed tokens + fused comp QKV
    run_gemm(xb, tWc, bc, nullptr, nullptr, compb, 4096, 1024, 4096, 4096, 4096, 0, 1024,
             1.f, 0, 1, 1, 0,0,0,0, 0,0, 0,0, 0,0, 0);
    run_gemm(compb, tW, biasqkv, nullptr, nullptr, cQKV, 4096, 3072, 1024,
             1024, 1024, 0, 3072, 1.f, 0, 1, 1, 0,0,0,0, 0,0, 0,0, 0,0, 0);

    // compressed attention (Qc = cQKV col 0, Kc = col 1024, lda/ldb = 3072)
    run_gemm(cQKV, cQKV + 1024, nullptr, nullptr, Sc, nullptr, 1024, 1024, 1024,
             3072, 3072, 1024, 0, SCALE, 0, BATCH, 1,
             1024L*3072, 0, 1024L*3072, 0, 1024L*1024, 0, 0,0, 0,0, 0);
    softmax_k<<<BATCH * 1024, 256>>>(Sc, Scb, 1024);
    trconv_h<<<dim3(32, 32, BATCH), trb>>>(cQKV + 2048, tVcb, 1024, 3072,
                                           1024L*3072, 1024L*1024);
    run_gemm(Scb, tVcb, nullptr, gates, nullptr, cPVb, 1024, 1024, 1024,
             1024, 1024, 0, 1024, 1.f, 0, BATCH, 1,
             1024L*1024, 0, 1024L*1024, 0, 0,0, 1024L*1024, 0, (long)SEQ*3, 0, 0);

    // selected branch
    gather_k<<<BATCH * KSEL, 128>>>(QKV, idxp, sQb, sKb, sVb);
    run_gemm(sQb, sKb, nullptr, nullptr, Ss, nullptr, 512, 512, 1024,
             1024, 1024, 512, 0, SCALE, 0, BATCH, 1,
             512L*1024, 0, 512L*1024, 0, 512L*512, 0, 0,0, 0,0, 0);
    softmax_k<<<BATCH * 512, 256>>>(Ss, Ssb, 512);
    trconv_h<<<dim3(32, 16, BATCH), trb>>>(sVb, tSvb, 512, 1024, 512L*1024, 1024L*512);
    run_gemm(Ssb, tSvb, nullptr, gates, nullptr, sPVb, 512, 1024, 512,
             512, 512, 0, 1024, 1.f, 0, BATCH, 1,
             512L*512, 0, 1024L*512, 0, 0,0, 512L*1024, 0, (long)SEQ*3, 0, 1);

    // window branch (Qf/Kf slices of fused QKV, lda 3072)
    trconv_h<<<dim3(32, 128, BATCH), trb>>>(QKV + 2048, tVfb, 4096, 3072,
                                            4096L*3072, 1024L*4096);
    run_gemm(QKV, QKV + 1024, nullptr, nullptr, Sw, nullptr, WIN, WIN, 1024,
             3072, 3072, WIN, 0, SCALE, 0, BATCH * NWIN, NWIN,
             (long)SEQ*3072, 128L*3072, (long)SEQ*3072, 128L*3072,
             (long)NWIN*WIN*WIN, (long)WIN*WIN, 0,0, 0,0, 0);
    softmax_k<<<BATCH * NWIN * WIN, 256>>>(Sw, Swb, WIN);
    run_gemm(Swb, tVfb, nullptr, gates, nullptr, wPVb, WIN, 1024, WIN,
             WIN, 4096, 0, 1024, 1.f, 0, BATCH * NWIN, NWIN,
             (long)NWIN*WIN*WIN, (long)WIN*WIN,
             1024L*4096, 128,
             0,0, (long)SEQ*1024, (long)WIN*1024,
             (long)SEQ*3, (long)WIN*3, 2);

    // output projection
    run_gemm(wPVb, tWo2, bo, nullptr, O, nullptr, (int)N_TOK, 1024, 1024,
             1024, 1024, 1024, 0, 1.f, 0, 1, 1, 0,0,0,0, 0,0, 0,0, 0,0, 0);
    run_gemm(cPVb, tWo0, nullptr, nullptr, O, nullptr, 1024, 1024, 1024,
             1024, 1024, 1024, 0, 1.f, 1, BATCH, 1,
             1024L*1024, 0, 0, 0, (long)SEQ*1024, 0, 0,0, 0,0, 0);
    run_gemm(sPVb, tWo1, nullptr, nullptr, O, nullptr, 512, 1024, 1024,
             1024, 1024, 1024, 0, 1.f, 1, BATCH, 1,
             512L*1024, 0, 0, 0, (long)SEQ*1024, 0, 0,0, 0,0, 0);

    // residual + layernorm
    final_ln_k<<<(int)N_TOK, 256>>>(O, x, outp);
}

// round 16
// speedup vs baseline: 2.7298x; 1.0967x over previous
#include <cuda_runtime.h>
#include <cuda_fp16.h>
#include <math.h>
#include <stdint.h>

// ---------------- problem constants ----------------
#define BATCH 4
#define SEQ   4096
#define HID_  1024
#define LC    1024
#define KSEL  512
#define WIN   256
#define NWIN  16
#define ROWS_W 2176   // QKV rows needed per batch by window branch (17*128)

static const long N_TOK = (long)BATCH * SEQ;

// ---------------- scratch layout (bytes) ----------------
constexpr long O_XB    = 0L;           // x fp16 (16384,1024)
constexpr long O_QKV   = 33554432L;    // partial QKV fp16 4x(2176,3072)
constexpr long O_CQKV  = 87031808L;    // comp QKV fp16 (4096,3072)
constexpr long O_COMPB = 112197632L;   // comp fp16 (4096,1024)
constexpr long O_TVFB  = 120586240L;   // Vf^T fp16 4x(1024,2176)
constexpr long O_TVCB  = 138412032L;   // Vc^T fp16 4x(1024,1024)
constexpr long O_SC    = 146800640L;   // comp scores fp32 4x(1024,1024)
constexpr long O_SCB   = 163577856L;   // comp P fp16
constexpr long O_CPVB  = 171966464L;   // comp PV fp16 (4096,1024)
constexpr long O_SXB   = 180355072L;   // sel x fp16 (2048,1024)
constexpr long O_SQKV  = 184549376L;   // sel QKV fp16 (2048,3072)
constexpr long O_TSVB  = 197132288L;   // sel V^T fp16 4x(1024,512)
constexpr long O_SS    = 201326592L;   // sel scores fp32 4x(512,512)
constexpr long O_SSB   = 205520896L;   // sel P fp16
constexpr long O_SPVB  = 207618048L;   // sel PV fp16 (2048,1024)
constexpr long O_SW    = 211812352L;   // win scores fp32 64x(256,256)
constexpr long O_SWB   = 228589568L;   // win P fp16
constexpr long O_WPVB  = 236978176L;   // win PV fp16 (16384,1024)
constexpr long O_O     = 270532608L;   // O fp32 (16384,1024)
constexpr long O_TW    = 337641472L;   // [Wq|Wk|Wv]^T fp16 (3072,1024)
constexpr long O_TWC   = 343932928L;   // Wc^T fp16 (1024,4096)
constexpr long O_TWO0  = 352321536L;
constexpr long O_TWO1  = 354418688L;
constexpr long O_TWO2  = 356515840L;
constexpr long O_GATES = 358612992L;
constexpr long O_SCOR  = 358809600L;
constexpr long O_BIAS  = 358875136L;
constexpr long TOTALB  = 358887424L;

__device__ __align__(1024) unsigned char g_scratch[TOTALB];
__device__ int g_idx[BATCH * KSEL];

typedef __half h16;

// ================= PTX helpers =================
__device__ __forceinline__ uint32_t smem_u32(const void* p) {
    uint32_t a;
    asm("{ .reg .u64 t; cvta.to.shared.u64 t, %1; cvt.u32.u64 %0, t; }" : "=r"(a) : "l"(p));
    return a;
}
__device__ __forceinline__ void cp16(uint32_t dst, const void* src) {
    asm volatile("cp.async.cg.shared.global [%0], [%1], 16;" :: "r"(dst), "l"(src));
}
#define CP_COMMIT() asm volatile("cp.async.commit_group;" ::: "memory")
#define CP_WAIT1()  asm volatile("cp.async.wait_group 1;" ::: "memory")

__device__ __forceinline__ void ldm4(uint32_t* r, uint32_t addr) {
    asm volatile("ldmatrix.sync.aligned.m8n8.x4.shared.b16 {%0,%1,%2,%3}, [%4];"
        : "=r"(r[0]), "=r"(r[1]), "=r"(r[2]), "=r"(r[3]) : "r"(addr));
}
__device__ __forceinline__ void mma16816(float* d, const uint32_t* a, const uint32_t* b) {
    asm volatile(
        "mma.sync.aligned.m16n8k16.row.col.f32.f16.f16.f32 "
        "{%0,%1,%2,%3}, {%4,%5,%6,%7}, {%8,%9}, {%0,%1,%2,%3};"
        : "+f"(d[0]), "+f"(d[1]), "+f"(d[2]), "+f"(d[3])
        : "r"(a[0]), "r"(a[1]), "r"(a[2]), "r"(a[3]), "r"(b[0]), "r"(b[1]));
}

// ================= pipelined HMMA GEMM (pure fp16) — R12-proven, unchanged =================
#define STAGE_B 32768
struct GP {
    const h16 *A, *B;
    const float *bias, *gate;
    float *Cf; h16 *Cb;
    int K, lda, ldb, ldcf, ldcb;
    float alpha;
    int accumulate, zdiv, gcomp;
    long aso, asi, bso, bsi, cfso, cfsi, cbso, cbsi, gso, gsi;
};

__device__ __forceinline__ void stage_load(uint32_t smb, int s, const h16* A, const h16* B,
                                           int lda, int ldb, int k0, int tid) {
    uint32_t sa = smb + s * STAGE_B;
    uint32_t sb2 = sa + 16384;
#pragma unroll
    for (int i = 0; i < 4; i++) {
        int idx = tid + i * 256;
        int row = idx >> 3, seg = idx & 7;
        cp16(sa + row * 128 + ((seg ^ (row & 7)) << 4), A + (long)row * lda + k0 + seg * 8);
    }
#pragma unroll
    for (int i = 0; i < 4; i++) {
        int idx = tid + i * 256;
        int row = idx >> 3, seg = idx & 7;
        cp16(sb2 + row * 128 + ((seg ^ (row & 7)) << 4), B + (long)row * ldb + k0 + seg * 8);
    }
    CP_COMMIT();
}

__device__ __forceinline__ uint32_t swzA(uint32_t base, int r, int cb) {
    return base + r * 128 + ((((cb >> 4) ^ (r & 7))) << 4);
}

__global__ void __launch_bounds__(256, 2) gemm_k(GP p) {
    extern __shared__ __align__(1024) char sm[];
    uint32_t smb = smem_u32(sm);
    const int tid = threadIdx.x, lane = tid & 31, wid = tid >> 5;
    const int wm = wid & 3, wn = wid >> 2;

    const long zo = blockIdx.z / p.zdiv, zi = blockIdx.z - zo * (long)p.zdiv;
    const h16* A = p.A + zo * p.aso + zi * p.asi + (long)blockIdx.y * 128 * p.lda;
    const h16* B = p.B + zo * p.bso + zi * p.bsi + (long)blockIdx.x * 128 * p.ldb;

    float acc[2][8][4];
#pragma unroll
    for (int mt = 0; mt < 2; mt++)
#pragma unroll
        for (int nt = 0; nt < 8; nt++)
#pragma unroll
            for (int r = 0; r < 4; r++) acc[mt][nt][r] = 0.f;

    const int nch = p.K >> 6;
    stage_load(smb, 0, A, B, p.lda, p.ldb, 0, tid);
    stage_load(smb, 1, A, B, p.lda, p.ldb, 64, tid);

    for (int c = 0; c < nch; c++) {
        CP_WAIT1();
        __syncthreads();
        if (c + 2 < nch) stage_load(smb, (c + 2) % 3, A, B, p.lda, p.ldb, (c + 2) * 64, tid);
        else CP_COMMIT();

        uint32_t sa = smb + (c % 3) * STAGE_B, sbB = sa + 16384;
#pragma unroll
        for (int ks = 0; ks < 4; ks++) {
            uint32_t aH[2][4];
            int ar = wm * 32 + (lane & 15);
            int acb = ks * 32 + ((lane >> 4) << 4);
#pragma unroll
            for (int mt = 0; mt < 2; mt++)
                ldm4(aH[mt], swzA(sa, ar + mt * 16, acb));
            int bcb = ks * 32 + (((lane >> 3) & 1) << 4);
#pragma unroll
            for (int nb = 0; nb < 4; nb++) {
                int brow = wn * 64 + nb * 16 + (lane & 7) + ((lane >> 4) << 3);
                uint32_t h4[4];
                ldm4(h4, swzA(sbB, brow, bcb));
#pragma unroll
                for (int sub = 0; sub < 2; sub++) {
                    int nt = nb * 2 + sub;
#pragma unroll
                    for (int mt = 0; mt < 2; mt++)
                        mma16816(acc[mt][nt], aH[mt], h4 + sub * 2);
                }
            }
        }
        __syncthreads();
    }

    // ---- epilogue ----
    const float* gb = p.gate ? (p.gate + zo * p.gso + zi * p.gsi) : nullptr;
    float* Cf = p.Cf ? (p.Cf + zo * p.cfso + zi * p.cfsi) : nullptr;
    h16* Cb = p.Cb ? (p.Cb + zo * p.cbso + zi * p.cbsi) : nullptr;
    const long rowBase = (long)blockIdx.y * 128 + wm * 32;
    const long colBase = (long)blockIdx.x * 128 + wn * 64;
    const int g = lane >> 2, t = lane & 3;
#pragma unroll
    for (int mt = 0; mt < 2; mt++) {
        long r0 = rowBase + mt * 16 + g, r1 = r0 + 8;
        float gv0 = gb ? gb[r0 * 3 + p.gcomp] : 1.f;
        float gv1 = gb ? gb[r1 * 3 + p.gcomp] : 1.f;
#pragma unroll
        for (int nt = 0; nt < 8; nt++) {
            long c = colBase + nt * 8 + t * 2;
            float b0 = p.bias ? p.bias[c] : 0.f;
            float b1 = p.bias ? p.bias[c + 1] : 0.f;
            float* d = acc[mt][nt];
            float v0 = p.alpha * d[0] + b0, v1 = p.alpha * d[1] + b1;
            float v2 = p.alpha * d[2] + b0, v3 = p.alpha * d[3] + b1;
            if (Cf) {
                long o0 = r0 * (long)p.ldcf + c, o1 = r1 * (long)p.ldcf + c;
                if (p.accumulate) { v0 += Cf[o0]; v1 += Cf[o0 + 1]; v2 += Cf[o1]; v3 += Cf[o1 + 1]; }
                v0 *= gv0; v1 *= gv0; v2 *= gv1; v3 *= gv1;
                *(float2*)(Cf + o0) = make_float2(v0, v1);
                *(float2*)(Cf + o1) = make_float2(v2, v3);
            } else {
                v0 *= gv0; v1 *= gv0; v2 *= gv1; v3 *= gv1;
            }
            if (Cb) {
                __half2 p0, p1;
                p0.x = __float2half_rn(v0); p0.y = __float2half_rn(v1);
                p1.x = __float2half_rn(v2); p1.y = __float2half_rn(v3);
                *(__half2*)(Cb + r0 * (long)p.ldcb + c) = p0;
                *(__half2*)(Cb + r1 * (long)p.ldcb + c) = p1;
            }
        }
    }
}

static void run_gemm(const h16* A, const h16* B, const float* bias, const float* gate,
                     float* Cf, h16* Cb, int M, int N, int K,
                     int lda, int ldb, int ldcf, int ldcb, float alpha,
                     int accum, int nz, int zdiv,
                     long aso, long asi, long bso, long bsi,
                     long cfso, long cfsi, long cbso, long cbsi,
                     long gso, long gsi, int gcomp) {
    GP p;
    p.A = A; p.B = B; p.bias = bias; p.gate = gate; p.Cf = Cf; p.Cb = Cb;
    p.K = K; p.lda = lda; p.ldb = ldb; p.ldcf = ldcf; p.ldcb = ldcb;
    p.alpha = alpha; p.accumulate = accum; p.zdiv = zdiv; p.gcomp = gcomp;
    p.aso = aso; p.asi = asi; p.bso = bso; p.bsi = bsi;
    p.cfso = cfso; p.cfsi = cfsi; p.cbso = cbso; p.cbsi = cbsi;
    p.gso = gso; p.gsi = gsi;
    dim3 grid(N / 128, M / 128, nz);
    gemm_k<<<grid, 256, 3 * STAGE_B>>>(p);
}

// ================= straight convert: fp32 -> fp16 =================
__global__ void conv_k(const float* __restrict__ in, h16* __restrict__ out, long n4) {
    long i = (long)blockIdx.x * 256 + threadIdx.x;
    if (i >= n4) return;
    long e = i * 4;
    float4 v = *(const float4*)(in + e);
    __half2 a, b;
    a.x = __float2half_rn(v.x); a.y = __float2half_rn(v.y);
    b.x = __float2half_rn(v.z); b.y = __float2half_rn(v.w);
    *(__half2*)(out + e) = a;
    *(__half2*)(out + e + 2) = b;
}

// ================= bias concat =================
__global__ void biascat_k(const float* __restrict__ bq, const float* __restrict__ bk,
                          const float* __restrict__ bv, float* __restrict__ out) {
    int i = blockIdx.x * 256 + threadIdx.x;
    if (i < 1024) out[i] = bq[i];
    else if (i < 2048) out[i] = bk[i - 1024];
    else if (i < 3072) out[i] = bv[i - 2048];
}

// ================= transpose convert: fp32 (R,C) -> fp16 (C,R) =================
__global__ void trconv_k(const float* __restrict__ in, h16* __restrict__ out,
                         int R, int C, long ibs, long obs) {
    __shared__ float tbuf[32][33];
    in += (long)blockIdx.z * ibs;
    out += (long)blockIdx.z * obs;
    int r0 = blockIdx.y * 32, c0 = blockIdx.x * 32;
    int tx = threadIdx.x, ty = threadIdx.y;
#pragma unroll
    for (int i = 0; i < 4; i++)
        tbuf[ty + i * 8][tx] = in[(long)(r0 + ty + i * 8) * C + c0 + tx];
    __syncthreads();
#pragma unroll
    for (int i = 0; i < 4; i++) {
        int oc = ty + i * 8;
        out[(long)(c0 + oc) * R + r0 + tx] = __float2half_rn(tbuf[tx][oc]);
    }
}

// ================= transpose fp16 (rows x 1024 cols; row stride ldi) -> fp16 (1024, Rout) =================
__global__ void trconv_h(const h16* __restrict__ in, h16* __restrict__ out,
                         int Rout, int ldi, long ibs, long obs) {
    __shared__ h16 tbuf[32][33];
    in += (long)blockIdx.z * ibs;
    out += (long)blockIdx.z * obs;
    int r0 = blockIdx.y * 32, c0 = blockIdx.x * 32;
    int tx = threadIdx.x, ty = threadIdx.y;
#pragma unroll
    for (int i = 0; i < 4; i++)
        tbuf[ty + i * 8][tx] = in[(long)(r0 + ty + i * 8) * ldi + c0 + tx];
    __syncthreads();
#pragma unroll
    for (int i = 0; i < 4; i++) {
        int oc = ty + i * 8;
        out[(long)(c0 + oc) * Rout + r0 + tx] = tbuf[tx][oc];
    }
}

// ================= gates + scores =================
__global__ void gates_scores_k(const float* __restrict__ x,
                               const float* __restrict__ Wg, const float* __restrict__ bg,
                               const float* __restrict__ Ws, const float* __restrict__ bs,
                               float* __restrict__ gates, float* __restrict__ scores) {
    int warp = threadIdx.x >> 5, lane = threadIdx.x & 31;
    long t = (long)blockIdx.x * 4 + warp;
    if (t >= N_TOK) return;
    const float* xr = x + t * HID_;
    float a0 = 0.f, a1 = 0.f, a2 = 0.f, a3 = 0.f;
    for (int d = lane; d < HID_; d += 32) {
        float xv = xr[d];
        a0 += xv * Wg[d * 3 + 0];
        a1 += xv * Wg[d * 3 + 1];
        a2 += xv * Wg[d * 3 + 2];
        a3 += xv * Ws[d];
    }
#pragma unroll
    for (int o = 16; o > 0; o >>= 1) {
        a0 += __shfl_down_sync(0xffffffffu, a0, o);
        a1 += __shfl_down_sync(0xffffffffu, a1, o);
        a2 += __shfl_down_sync(0xffffffffu, a2, o);
        a3 += __shfl_down_sync(0xffffffffu, a3, o);
    }
    if (lane == 0) {
        float g0 = 1.f / (1.f + expf(-(a0 + bg[0])));
        float g1 = 1.f / (1.f + expf(-(a1 + bg[1])));
        float g2 = 1.f / (1.f + expf(-(a2 + bg[2])));
        float s = g0 + g1 + g2 + 1e-6f;
        gates[t * 3 + 0] = g0 / s;
        gates[t * 3 + 1] = g1 / s;
        gates[t * 3 + 2] = g2 / s;
        scores[t] = a3 + bs[0];
    }
}

// ================= exact top-k =================
__device__ __forceinline__ bool before_f(float sa, int ia, float sb, int ib) {
    return (sa > sb) || (sa == sb && ia < ib);
}
__global__ void __launch_bounds__(512) topk_k(const float* __restrict__ scores, int* __restrict__ idx_out) {
    __shared__ float s[SEQ];
    __shared__ int id[SEQ];
    __shared__ int sel[KSEL];
    int b = blockIdx.x, tid = threadIdx.x;
    for (int i = tid; i < SEQ; i += 512) { s[i] = scores[(long)b * SEQ + i]; id[i] = i; }
    __syncthreads();
    for (int k = 2; k <= SEQ; k <<= 1)
        for (int j = k >> 1; j > 0; j >>= 1) {
            for (int i = tid; i < SEQ; i += 512) {
                int ixj = i ^ j;
                if (ixj > i) {
                    bool up = ((i & k) == 0);
                    bool ib = before_f(s[i], id[i], s[ixj], id[ixj]);
                    if (up ? !ib : ib) {
                        float ts = s[i]; s[i] = s[ixj]; s[ixj] = ts;
                        int ti = id[i]; id[i] = id[ixj]; id[ixj] = ti;
                    }
                }
            }
            __syncthreads();
        }
    if (tid < KSEL) sel[tid] = id[tid];
    __syncthreads();
    for (int k = 2; k <= KSEL; k <<= 1)
        for (int j = k >> 1; j > 0; j >>= 1) {
            int i = tid;
            if (i < KSEL) {
                int ixj = i ^ j;
                if (ixj > i) {
                    bool up = ((i & k) == 0);
                    if (up ? (sel[i] > sel[ixj]) : (sel[i] < sel[ixj])) {
                        int tt = sel[i]; sel[i] = sel[ixj]; sel[ixj] = tt;
                    }
                }
            }
            __syncthreads();
        }
    if (tid < KSEL) idx_out[b * KSEL + tid] = sel[tid];
}

// ================= gather x rows (fp16) for selected branch =================
__global__ void gather_x_k(const h16* __restrict__ xb, const int* __restrict__ idx,
                           h16* __restrict__ sx) {
    int r = blockIdx.x;
    int b = r >> 9;
    long srow = (long)b * SEQ + idx[r];
    int tid = threadIdx.x;   // 128 threads, row = 128 uint4
    ((uint4*)(sx + (long)r * 1024))[tid] = ((const uint4*)(xb + srow * 1024))[tid];
}

// ================= softmax (fp32 in, fp16 out) =================
__global__ void softmax_k(const float* __restrict__ S, h16* __restrict__ Pb, int N) {
    __shared__ float buf[1024];
    __shared__ float red[256];
    long base = (long)blockIdx.x * N;
    int tid = threadIdx.x;
    float m = -1e30f;
    for (int i = tid; i < N; i += 256) { float xv = S[base + i]; buf[i] = xv; m = fmaxf(m, xv); }
    red[tid] = m; __syncthreads();
    for (int o = 128; o > 0; o >>= 1) { if (tid < o) red[tid] = fmaxf(red[tid], red[tid + o]); __syncthreads(); }
    m = red[0]; __syncthreads();
    float sum = 0.f;
    for (int i = tid; i < N; i += 256) { float e = expf(buf[i] - m); buf[i] = e; sum += e; }
    red[tid] = sum; __syncthreads();
    for (int o = 128; o > 0; o >>= 1) { if (tid < o) red[tid] += red[tid + o]; __syncthreads(); }
    float inv = 1.f / red[0];
    __syncthreads();
    for (int i = tid; i < N; i += 256)
        Pb[base + i] = __float2half_rn(buf[i] * inv);
}

// ================= residual + layernorm =================
__global__ void final_ln_k(const float* __restrict__ O, const float* __restrict__ x,
                           float* __restrict__ out) {
    long base = (long)blockIdx.x * HID_;
    int tid = threadIdx.x;
    float y[4];
    float s = 0.f, ss = 0.f;
#pragma unroll
    for (int i = 0; i < 4; i++) {
        int c = tid + i * 256;
        float v = 0.5f * (O[base + c] + x[base + c]);
        y[i] = v; s += v; ss += v * v;
    }
    __shared__ float rs[32], rss[32];
    int lane = tid & 31, warp = tid >> 5;
#pragma unroll
    for (int o = 16; o > 0; o >>= 1) {
        s += __shfl_down_sync(0xffffffffu, s, o);
        ss += __shfl_down_sync(0xffffffffu, ss, o);
    }
    if (lane == 0) { rs[warp] = s; rss[warp] = ss; }
    __syncthreads();
    if (warp == 0) {
        s = (lane < 8) ? rs[lane] : 0.f;
        ss = (lane < 8) ? rss[lane] : 0.f;
#pragma unroll
        for (int o = 4; o > 0; o >>= 1) {
            s += __shfl_down_sync(0xffffffffu, s, o);
            ss += __shfl_down_sync(0xffffffffu, ss, o);
        }
        if (lane == 0) { rs[0] = s; rss[0] = ss; }
    }
    __syncthreads();
    float mu = rs[0] * (1.f / HID_);
    float var = rss[0] * (1.f / HID_) - mu * mu;
    float inv = rsqrtf(var + 1e-6f);
#pragma unroll
    for (int i = 0; i < 4; i++) {
        int c = tid + i * 256;
        out[base + c] = (y[i] - mu) * inv;
    }
}

// ================= launch =================
extern "C" void kernel_launch(void* const* d_in, const int* in_sizes, int n_in,
                              void* d_out, int out_size) {
    const float* x  = (const float*)d_in[0];
    const float* Wq = (const float*)d_in[1];
    const float* bq = (const float*)d_in[2];
    const float* Wk = (const float*)d_in[3];
    const float* bk = (const float*)d_in[4];
    const float* Wv = (const float*)d_in[5];
    const float* bv = (const float*)d_in[6];
    const float* Wo = (const float*)d_in[7];
    const float* bo = (const float*)d_in[8];
    const float* Wg = (const float*)d_in[9];
    const float* bg = (const float*)d_in[10];
    const float* Wc = (const float*)d_in[11];
    const float* bc = (const float*)d_in[12];
    const float* Ws = (const float*)d_in[13];
    const float* bs = (const float*)d_in[14];

    cudaFuncSetAttribute(gemm_k, cudaFuncAttributeMaxDynamicSharedMemorySize, 3 * STAGE_B);

    unsigned char* G; cudaGetSymbolAddress((void**)&G, g_scratch);
    int* idxp; cudaGetSymbolAddress((void**)&idxp, g_idx);

    h16* xb    = (h16*)(G + O_XB);
    h16* QKV   = (h16*)(G + O_QKV);     // 4 batches x (2176,3072)
    h16* cQKV  = (h16*)(G + O_CQKV);
    h16* compb = (h16*)(G + O_COMPB);
    h16* tVfb  = (h16*)(G + O_TVFB);    // 4 x (1024,2176)
    h16* tVcb  = (h16*)(G + O_TVCB);
    float* Sc  = (float*)(G + O_SC);
    h16* Scb   = (h16*)(G + O_SCB);
    h16* cPVb  = (h16*)(G + O_CPVB);
    h16* sxb   = (h16*)(G + O_SXB);
    h16* sQKV  = (h16*)(G + O_SQKV);
    h16* tSvb  = (h16*)(G + O_TSVB);
    float* Ss  = (float*)(G + O_SS);
    h16* Ssb   = (h16*)(G + O_SSB);
    h16* sPVb  = (h16*)(G + O_SPVB);
    float* Sw  = (float*)(G + O_SW);
    h16* Swb   = (h16*)(G + O_SWB);
    h16* wPVb  = (h16*)(G + O_WPVB);
    float* O   = (float*)(G + O_O);
    h16* tW    = (h16*)(G + O_TW);
    h16* tWc   = (h16*)(G + O_TWC);
    h16* tWo0  = (h16*)(G + O_TWO0);
    h16* tWo1  = (h16*)(G + O_TWO1);
    h16* tWo2  = (h16*)(G + O_TWO2);
    float* gates  = (float*)(G + O_GATES);
    float* scores = (float*)(G + O_SCOR);
    float* biasqkv = (float*)(G + O_BIAS);
    float* outp = (float*)d_out;

    const float SCALE = 0.125f;
    dim3 trb(32, 8);
    const long QKV_BS = (long)ROWS_W * 3072;   // per-batch QKV stride

    // launches 1-5, then launch 6 = partial fused QKV GEMM (ncu target)
    conv_k<<<(int)((N_TOK * HID_ / 4 + 255) / 256), 256>>>(x, xb, N_TOK * HID_ / 4);
    biascat_k<<<12, 256>>>(bq, bk, bv, biasqkv);
    trconv_k<<<dim3(32, 32, 1), trb>>>(Wq, tW, 1024, 1024, 0, 0);
    trconv_k<<<dim3(32, 32, 1), trb>>>(Wk, tW + 1024L * 1024, 1024, 1024, 0, 0);
    trconv_k<<<dim3(32, 32, 1), trb>>>(Wv, tW + 2048L * 1024, 1024, 1024, 0, 0);
    // fused QKV projection over window-needed rows only: per batch (2176,3072)
    run_gemm(xb, tW, biasqkv, nullptr, nullptr, QKV, ROWS_W, 3072, 1024,
             1024, 1024, 0, 3072, 1.f, 0, BATCH, 1,
             (long)SEQ * 1024, 0, 0, 0, 0, 0, QKV_BS, 0, 0, 0, 0);

    trconv_k<<<dim3(32, 128, 1), trb>>>(Wc, tWc, 4096, 1024, 0, 0);
    trconv_k<<<dim3(32, 32, 1), trb>>>(Wo, tWo0, 1024, 1024, 0, 0);
    trconv_k<<<dim3(32, 32, 1), trb>>>(Wo + 1024L * 1024, tWo1, 1024, 1024, 0, 0);
    trconv_k<<<dim3(32, 32, 1), trb>>>(Wo + 2048L * 1024, tWo2, 1024, 1024, 0, 0);

    gates_scores_k<<<(int)(N_TOK / 4), 128>>>(x, Wg, bg, Ws, bs, gates, scores);
    topk_k<<<BATCH, 512>>>(scores, idxp);

    // compressed tokens + fused comp QKV
    run_gemm(xb, tWc, bc, nullptr, nullptr, compb, 4096, 1024, 4096, 4096, 4096, 0, 1024,
             1.f, 0, 1, 1, 0,0,0,0, 0,0, 0,0, 0,0, 0);
    run_gemm(compb, tW, biasqkv, nullptr, nullptr, cQKV, 4096, 3072, 1024,
             1024, 1024, 0, 3072, 1.f, 0, 1, 1, 0,0,0,0, 0,0, 0,0, 0,0, 0);

    // compressed attention
    run_gemm(cQKV, cQKV + 1024, nullptr, nullptr, Sc, nullptr, 1024, 1024, 1024,
             3072, 3072, 1024, 0, SCALE, 0, BATCH, 1,
             1024L*3072, 0, 1024L*3072, 0, 1024L*1024, 0, 0,0, 0,0, 0);
    softmax_k<<<BATCH * 1024, 256>>>(Sc, Scb, 1024);
    trconv_h<<<dim3(32, 32, BATCH), trb>>>(cQKV + 2048, tVcb, 1024, 3072,
                                           1024L*3072, 1024L*1024);
    run_gemm(Scb, tVcb, nullptr, gates, nullptr, cPVb, 1024, 1024, 1024,
             1024, 1024, 0, 1024, 1.f, 0, BATCH, 1,
             1024L*1024, 0, 1024L*1024, 0, 0,0, 1024L*1024, 0, (long)SEQ*3, 0, 0);

    // selected branch: gather x rows, project QKV of selected tokens directly
    gather_x_k<<<BATCH * KSEL, 128>>>(xb, idxp, sxb);
    run_gemm(sxb, tW, biasqkv, nullptr, nullptr, sQKV, BATCH * KSEL, 3072, 1024,
             1024, 1024, 0, 3072, 1.f, 0, 1, 1, 0,0,0,0, 0,0, 0,0, 0,0, 0);
    run_gemm(sQKV, sQKV + 1024, nullptr, nullptr, Ss, nullptr, 512, 512, 1024,
             3072, 3072, 512, 0, SCALE, 0, BATCH, 1,
             512L*3072, 0, 512L*3072, 0, 512L*512, 0, 0,0, 0,0, 0);
    softmax_k<<<BATCH * 512, 256>>>(Ss, Ssb, 512);
    trconv_h<<<dim3(32, 16, BATCH), trb>>>(sQKV + 2048, tSvb, 512, 3072,
                                           512L*3072, 1024L*512);
    run_gemm(Ssb, tSvb, nullptr, gates, nullptr, sPVb, 512, 1024, 512,
             512, 512, 0, 1024, 1.f, 0, BATCH, 1,
             512L*512, 0, 1024L*512, 0, 0,0, 512L*1024, 0, (long)SEQ*3, 0, 1);

    // window branch (Q/K slices of partial QKV; V^T over 2176 rows)
    trconv_h<<<dim3(32, ROWS_W / 32, BATCH), trb>>>(QKV + 2048, tVfb, ROWS_W, 3072,
                                                    QKV_BS, 1024L * ROWS_W);
    run_gemm(QKV, QKV + 1024, nullptr, nullptr, Sw, nullptr, WIN, WIN, 1024,
             3072, 3072, WIN, 0, SCALE, 0, BATCH * NWIN, NWIN,
             QKV_BS, 128L*3072, QKV_BS, 128L*3072,
             (long)NWIN*WIN*WIN, (long)WIN*WIN, 0,0, 0,0, 0);
    softmax_k<<<BATCH * NWIN * WIN, 256>>>(Sw, Swb, WIN);
    run_gemm(Swb, tVfb, nullptr, gates, nullptr, wPVb, WIN, 1024, WIN,
             WIN, ROWS_W, 0, 1024, 1.f, 0, BATCH * NWIN, NWIN,
             (long)NWIN*WIN*WIN, (long)WIN*WIN,
             1024L * ROWS_W, 128,
             0,0, (long)SEQ*1024, (long)WIN*1024,
             (long)SEQ*3, (long)WIN*3, 2);

    // output projection
    run_gemm(wPVb, tWo2, bo, nullptr, O, nullptr, (int)N_TOK, 1024, 1024,
             1024, 1024, 1024, 0, 1.f, 0, 1, 1, 0,0,0,0, 0,0, 0,0, 0,0, 0);
    run_gemm(cPVb, tWo0, nullptr, nullptr, O, nullptr, 1024, 1024, 1024,
             1024, 1024, 1024, 0, 1.f, 1, BATCH, 1,
             1024L*1024, 0, 0, 0, (long)SEQ*1024, 0, 0,0, 0,0, 0);
    run_gemm(sPVb, tWo1, nullptr, nullptr, O, nullptr, 512, 1024, 1024,
             1024, 1024, 1024, 0, 1.f, 1, BATCH, 1,
             512L*1024, 0, 0, 0, (long)SEQ*1024, 0, 0,0, 0,0, 0);

    // residual + layernorm
    final_ln_k<<<(int)N_TOK, 256>>>(O, x, outp);
}